// round 7
// baseline (speedup 1.0000x reference)
#include <cuda_runtime.h>
#include <cuda_bf16.h>
#include <math.h>
#include <stdint.h>

#define Lc 26
#define Tc 512
#define Dc 768
#define NHc 12
#define NGc 4
#define GSc 3
#define HDc 64
#define FFc 2048
#define CACHEc 1536
#define Sc 2048
#define Vocab 32000
#define WINc 512
#define QKVW 1280
typedef __nv_bfloat16 bf16;

#define SZ_WQKV 25559040
#define SZ_WOUT 15335424
#define SZ_WFF  40894464
#define SZ_WLM  24576000

// ---------------- scratch ----------------
__device__ float g_h[Tc * Dc];
__device__ float g_qkv[Tc * QKVW];
__device__ float g_t1[Tc * Dc];
__device__ bf16 bx_h[Tc * Dc], bx_l[Tc * Dc];
__device__ bf16 bat_h[Tc * Dc], bat_l[Tc * Dc];
__device__ bf16 bgt_h[Tc * FFc], bgt_l[Tc * FFc];
__device__ bf16 bq_h[NHc * Tc * HDc], bq_l[NHc * Tc * HDc];
__device__ bf16 bk_h[NGc * Sc * HDc], bk_l[NGc * Sc * HDc];
__device__ bf16 bv_h[NGc * HDc * Sc], bv_l[NGc * HDc * Sc];
__device__ bf16 wqkv_h[SZ_WQKV], wqkv_l[SZ_WQKV];
__device__ bf16 wout_h[SZ_WOUT], wout_l[SZ_WOUT];
__device__ bf16 wgt_h[SZ_WFF], wgt_l[SZ_WFF];
__device__ bf16 wup_h[SZ_WFF], wup_l[SZ_WFF];
__device__ bf16 wdn_h[SZ_WFF], wdn_l[SZ_WFF];
__device__ bf16 wlm_h[SZ_WLM], wlm_l[SZ_WLM];

// ---------------- asm helpers ----------------
__device__ __forceinline__ uint32_t cvta(const void* p) {
    return (uint32_t)__cvta_generic_to_shared(p);
}
#define LDSM4(r, a) asm volatile( \
    "ldmatrix.sync.aligned.m8n8.x4.shared.b16 {%0,%1,%2,%3},[%4];\n" \
    : "=r"((r)[0]), "=r"((r)[1]), "=r"((r)[2]), "=r"((r)[3]) : "r"(a))
#define LDSM4T(r, a) asm volatile( \
    "ldmatrix.sync.aligned.m8n8.x4.trans.shared.b16 {%0,%1,%2,%3},[%4];\n" \
    : "=r"((r)[0]), "=r"((r)[1]), "=r"((r)[2]), "=r"((r)[3]) : "r"(a))
#define MMA16(c, a, b0, b1) asm volatile( \
    "mma.sync.aligned.m16n8k16.row.col.f32.bf16.bf16.f32 " \
    "{%0,%1,%2,%3},{%4,%5,%6,%7},{%8,%9},{%0,%1,%2,%3};\n" \
    : "+f"((c)[0]), "+f"((c)[1]), "+f"((c)[2]), "+f"((c)[3]) \
    : "r"((a)[0]), "r"((a)[1]), "r"((a)[2]), "r"((a)[3]), "r"(b0), "r"(b1))
#define CPA16(d, s) asm volatile("cp.async.cg.shared.global [%0],[%1],16;\n" :: "r"(d), "l"(s))
#define CPCOMMIT() asm volatile("cp.async.commit_group;\n")
#define CPWAIT(n) asm volatile("cp.async.wait_group %0;\n" :: "n"(n))

__device__ __forceinline__ void splitstore(bf16* ph, bf16* pl, size_t i, float v) {
    bf16 h = __float2bfloat16(v);
    ph[i] = h;
    pl[i] = __float2bfloat16(v - __bfloat162float(h));
}

__device__ __forceinline__ float blockReduceSum(float v) {
    __shared__ float sh[8];
    __syncthreads();
    int lane = threadIdx.x & 31, w = threadIdx.x >> 5;
#pragma unroll
    for (int o = 16; o; o >>= 1) v += __shfl_down_sync(0xffffffffu, v, o);
    if (lane == 0) sh[w] = v;
    __syncthreads();
    int nw = blockDim.x >> 5;
    if (w == 0) {
        v = (lane < nw) ? sh[lane] : 0.f;
#pragma unroll
        for (int o = 4; o; o >>= 1) v += __shfl_down_sync(0xffffffffu, v, o);
        if (lane == 0) sh[0] = v;
    }
    __syncthreads();
    return sh[0];
}

// ---------------- elementwise ----------------
__global__ void k_split4(const float* __restrict__ s, bf16* __restrict__ hi,
                         bf16* __restrict__ lo, int n4) {
    int i = blockIdx.x * blockDim.x + threadIdx.x;
    if (i >= n4) return;
    float4 v = ((const float4*)s)[i];
    size_t b = (size_t)i * 4;
    splitstore(hi, lo, b, v.x);
    splitstore(hi, lo, b + 1, v.y);
    splitstore(hi, lo, b + 2, v.z);
    splitstore(hi, lo, b + 3, v.w);
}

__global__ void k_init(const float* __restrict__ e, const float* __restrict__ w,
                       float* __restrict__ h, bf16* __restrict__ oh, bf16* __restrict__ ol) {
    int row = blockIdx.x;
    const float* x = e + row * Dc;
    float ss = 0.f;
    for (int d = threadIdx.x; d < Dc; d += blockDim.x) { float v = x[d]; ss += v * v; }
    float rs = rsqrtf(blockReduceSum(ss) / Dc + 1e-6f);
    for (int d = threadIdx.x; d < Dc; d += blockDim.x) {
        float v = x[d];
        h[row * Dc + d] = v;
        splitstore(oh, ol, (size_t)row * Dc + d, v * rs * (1.f + w[d]));
    }
}

__global__ void k_fuse(float* __restrict__ h, const float* __restrict__ t1,
                       const float* __restrict__ wpost, const float* __restrict__ wpre,
                       bf16* __restrict__ oh, bf16* __restrict__ ol) {
    int row = blockIdx.x;
    const float* x = t1 + row * Dc;
    float ss = 0.f;
    for (int d = threadIdx.x; d < Dc; d += blockDim.x) { float v = x[d]; ss += v * v; }
    float rs = rsqrtf(blockReduceSum(ss) / Dc + 1e-6f);
    float ss2 = 0.f;
    for (int d = threadIdx.x; d < Dc; d += blockDim.x) {
        float hv = h[row * Dc + d] + x[d] * rs * (1.f + wpost[d]);
        h[row * Dc + d] = hv;
        ss2 += hv * hv;
    }
    float rs2 = rsqrtf(blockReduceSum(ss2) / Dc + 1e-6f);
    for (int d = threadIdx.x; d < Dc; d += blockDim.x)
        splitstore(oh, ol, (size_t)row * Dc + d, h[row * Dc + d] * rs2 * (1.f + wpre[d]));
}

__global__ void k_convkv(const float* __restrict__ ks, const float* __restrict__ vs,
                         bf16* __restrict__ kh, bf16* __restrict__ kl,
                         bf16* __restrict__ vh, bf16* __restrict__ vl) {
    int idx = blockIdx.x * blockDim.x + threadIdx.x;
    if (idx < 98304) {
        int i4 = idx * 4;
        int g = i4 / (CACHEc * HDc), r = i4 - g * (CACHEc * HDc);
        size_t dst = (size_t)g * Sc * HDc + r;
        float4 v = ((const float4*)ks)[idx];
        splitstore(kh, kl, dst, v.x); splitstore(kh, kl, dst + 1, v.y);
        splitstore(kh, kl, dst + 2, v.z); splitstore(kh, kl, dst + 3, v.w);
    } else if (idx < 196608) {
        int j4 = (idx - 98304) * 4;
        int row = j4 / CACHEc, c = j4 - row * CACHEc;
        size_t dst = (size_t)row * Sc + c;
        float4 v = ((const float4*)vs)[idx - 98304];
        splitstore(vh, vl, dst, v.x); splitstore(vh, vl, dst + 1, v.y);
        splitstore(vh, vl, dst + 2, v.z); splitstore(vh, vl, dst + 3, v.w);
    }
}

__global__ void k_qkprep(const float* __restrict__ qkv,
                         const float* __restrict__ qw, const float* __restrict__ kw,
                         const float* __restrict__ cos_, const float* __restrict__ sin_) {
    int t = blockIdx.x, g = blockIdx.y, d = threadIdx.x;
    const float* base = qkv + ((t * NGc + g) * (GSc + 2)) * HDc;
    __shared__ float sh[HDc];
    __shared__ float r2[2];
    float c = cos_[t * HDc + d], s = sin_[t * HDc + d];
#pragma unroll
    for (int j = 0; j <= GSc; j++) {
        float v = base[j * HDc + d];
        float sq = v * v;
#pragma unroll
        for (int o = 16; o; o >>= 1) sq += __shfl_down_sync(0xffffffffu, sq, o);
        if ((d & 31) == 0) r2[d >> 5] = sq;
        __syncthreads();
        float rs = rsqrtf((r2[0] + r2[1]) * (1.f / HDc) + 1e-6f);
        const float* wgt = (j < GSc) ? qw : kw;
        float nv = v * rs * (1.f + wgt[d]);
        sh[d] = nv;
        __syncthreads();
        float rot = (d < 32) ? -sh[d + 32] : sh[d - 32];
        float outv = nv * c + rot * s;
        if (j < GSc) splitstore(bq_h, bq_l, ((size_t)(g * GSc + j) * Tc + t) * HDc + d, outv);
        else splitstore(bk_h, bk_l, ((size_t)g * Sc + CACHEc + t) * HDc + d, outv);
        __syncthreads();
    }
    splitstore(bv_h, bv_l, (size_t)(g * HDc + d) * Sc + CACHEc + t, base[(GSc + 1) * HDc + d]);
}

// ============ templated GEMM: BM x 64 tile, BK=32, 256 thr ============
template <int BM, int WMW>
__global__ void __launch_bounds__(256) k_mm_t(const bf16* __restrict__ Ah,
                                              const bf16* __restrict__ Al,
                                              const bf16* __restrict__ Bh,
                                              const bf16* __restrict__ Bl,
                                              float* __restrict__ C, int N, int K) {
    constexpr int WNW = 8 / WMW;
    constexpr int WROWS = BM / WMW;
    constexpr int WCOLS = 64 / WNW;
    constexpr int N8 = WCOLS / 8;
    constexpr int NB = WCOLS / 16;
    constexpr int AJ = BM / 64;
    extern __shared__ char dsm[];
    bf16* sA = (bf16*)dsm;
    bf16* sB = (bf16*)(dsm + 2 * 2 * BM * 40 * 2);
#define SAi(st, p, r, c) (sA + ((((st)*2 + (p)) * BM + (r)) * 40 + (c)))
#define SBi(st, p, r, c) (sB + ((((st)*2 + (p)) * 32 + (r)) * 72 + (c)))
    int tid = threadIdx.x, lane = tid & 31, warp = tid >> 5;
    int wm = warp % WMW, wn = warp / WMW;
    int bm = blockIdx.y * BM, bn = blockIdx.x * 64;
    int nIt = K >> 5;
    int br = tid >> 3, bc = (tid & 7) << 3;
    const bf16* pBh = Bh + (size_t)br * N + bn + bc;
    const bf16* pBl = Bl + (size_t)br * N + bn + bc;
    float acc[2][N8][4] = {};
#pragma unroll
    for (int j = 0; j < AJ; j++) {
        int id = tid + j * 256, r = id >> 2, c = (id & 3) << 3;
        CPA16(cvta(SAi(0, 0, r, c)), Ah + (size_t)(bm + r) * K + c);
        CPA16(cvta(SAi(0, 1, r, c)), Al + (size_t)(bm + r) * K + c);
    }
    CPA16(cvta(SBi(0, 0, br, bc)), pBh);
    CPA16(cvta(SBi(0, 1, br, bc)), pBl);
    CPCOMMIT();
    for (int it = 0; it < nIt; it++) {
        int st = it & 1;
        if (it + 1 < nIt) {
            int k0 = (it + 1) << 5;
#pragma unroll
            for (int j = 0; j < AJ; j++) {
                int id = tid + j * 256, r = id >> 2, c = (id & 3) << 3;
                CPA16(cvta(SAi(st ^ 1, 0, r, c)), Ah + (size_t)(bm + r) * K + k0 + c);
                CPA16(cvta(SAi(st ^ 1, 1, r, c)), Al + (size_t)(bm + r) * K + k0 + c);
            }
            CPA16(cvta(SBi(st ^ 1, 0, br, bc)), pBh + (size_t)k0 * N);
            CPA16(cvta(SBi(st ^ 1, 1, br, bc)), pBl + (size_t)k0 * N);
            CPCOMMIT(); CPWAIT(1);
        } else CPWAIT(0);
        __syncthreads();
#pragma unroll
        for (int kp = 0; kp < 2; kp++) {
            uint32_t ah2[2][4], al2[2][4], bh2[4 * NB], bl2[4 * NB];
#pragma unroll
            for (int mt = 0; mt < 2; mt++) {
                int r = wm * WROWS + mt * 16 + (lane & 15), c = kp * 16 + ((lane >> 4) << 3);
                LDSM4(ah2[mt], cvta(SAi(st, 0, r, c)));
                LDSM4(al2[mt], cvta(SAi(st, 1, r, c)));
            }
            int bg = lane >> 3;
            int kr = kp * 16 + ((bg & 1) << 3) + (lane & 7);
#pragma unroll
            for (int nb = 0; nb < NB; nb++) {
                int nc = wn * WCOLS + nb * 16 + ((bg >> 1) << 3);
                LDSM4T(&bh2[nb * 4], cvta(SBi(st, 0, kr, nc)));
                LDSM4T(&bl2[nb * 4], cvta(SBi(st, 1, kr, nc)));
            }
#pragma unroll
            for (int mt = 0; mt < 2; mt++)
#pragma unroll
                for (int nt = 0; nt < N8; nt++) {
                    int f = (nt >> 1) * 4 + ((nt & 1) << 1);
                    MMA16(acc[mt][nt], ah2[mt], bh2[f], bh2[f + 1]);
                    MMA16(acc[mt][nt], ah2[mt], bl2[f], bl2[f + 1]);
                    MMA16(acc[mt][nt], al2[mt], bh2[f], bh2[f + 1]);
                }
        }
        __syncthreads();
    }
#pragma unroll
    for (int mt = 0; mt < 2; mt++)
#pragma unroll
        for (int nt = 0; nt < N8; nt++) {
            int r0 = bm + wm * WROWS + mt * 16 + (lane >> 2);
            int c0 = bn + wn * WCOLS + nt * 8 + 2 * (lane & 3);
            *(float2*)(C + (size_t)r0 * N + c0) = make_float2(acc[mt][nt][0], acc[mt][nt][1]);
            *(float2*)(C + (size_t)(r0 + 8) * N + c0) = make_float2(acc[mt][nt][2], acc[mt][nt][3]);
        }
#undef SAi
#undef SBi
}

// ============ dual GEMM (gate|up) + gelu*mul, BM=128 (4m x 2n warps) ============
__global__ void __launch_bounds__(256) k_mmff(const bf16* __restrict__ Ah,
                                              const bf16* __restrict__ Al,
                                              const bf16* __restrict__ B0h,
                                              const bf16* __restrict__ B0l,
                                              const bf16* __restrict__ B1h,
                                              const bf16* __restrict__ B1l,
                                              bf16* __restrict__ Oh, bf16* __restrict__ Ol) {
    constexpr int BM = 128;
    extern __shared__ char dsm[];
    bf16* sA = (bf16*)dsm;
    bf16* sB0 = (bf16*)(dsm + 2 * 2 * BM * 40 * 2);
    bf16* sB1 = (bf16*)(dsm + 2 * 2 * BM * 40 * 2 + 2 * 2 * 32 * 72 * 2);
#define SAi(st, p, r, c) (sA + ((((st)*2 + (p)) * BM + (r)) * 40 + (c)))
#define SB0i(st, p, r, c) (sB0 + ((((st)*2 + (p)) * 32 + (r)) * 72 + (c)))
#define SB1i(st, p, r, c) (sB1 + ((((st)*2 + (p)) * 32 + (r)) * 72 + (c)))
    const int N = FFc, K = Dc;
    int tid = threadIdx.x, lane = tid & 31, warp = tid >> 5;
    int wm = warp & 3, wn = warp >> 2;
    int bm = blockIdx.y * BM, bn = blockIdx.x * 64;
    int br = tid >> 3, bc = (tid & 7) << 3;
    size_t boff = (size_t)br * N + bn + bc;
    float ag[2][4][4] = {}, au[2][4][4] = {};
#pragma unroll
    for (int j = 0; j < 2; j++) {
        int id = tid + j * 256, r = id >> 2, c = (id & 3) << 3;
        CPA16(cvta(SAi(0, 0, r, c)), Ah + (size_t)(bm + r) * K + c);
        CPA16(cvta(SAi(0, 1, r, c)), Al + (size_t)(bm + r) * K + c);
    }
    CPA16(cvta(SB0i(0, 0, br, bc)), B0h + boff); CPA16(cvta(SB0i(0, 1, br, bc)), B0l + boff);
    CPA16(cvta(SB1i(0, 0, br, bc)), B1h + boff); CPA16(cvta(SB1i(0, 1, br, bc)), B1l + boff);
    CPCOMMIT();
    for (int it = 0; it < (K >> 5); it++) {
        int st = it & 1;
        if (it + 1 < (K >> 5)) {
            int k0 = (it + 1) << 5;
#pragma unroll
            for (int j = 0; j < 2; j++) {
                int id = tid + j * 256, r = id >> 2, c = (id & 3) << 3;
                CPA16(cvta(SAi(st ^ 1, 0, r, c)), Ah + (size_t)(bm + r) * K + k0 + c);
                CPA16(cvta(SAi(st ^ 1, 1, r, c)), Al + (size_t)(bm + r) * K + k0 + c);
            }
            CPA16(cvta(SB0i(st ^ 1, 0, br, bc)), B0h + boff + (size_t)k0 * N);
            CPA16(cvta(SB0i(st ^ 1, 1, br, bc)), B0l + boff + (size_t)k0 * N);
            CPA16(cvta(SB1i(st ^ 1, 0, br, bc)), B1h + boff + (size_t)k0 * N);
            CPA16(cvta(SB1i(st ^ 1, 1, br, bc)), B1l + boff + (size_t)k0 * N);
            CPCOMMIT(); CPWAIT(1);
        } else CPWAIT(0);
        __syncthreads();
#pragma unroll
        for (int kp = 0; kp < 2; kp++) {
            uint32_t ah2[2][4], al2[2][4], b0h[8], b0l[8], b1h[8], b1l[8];
#pragma unroll
            for (int mt = 0; mt < 2; mt++) {
                int r = wm * 32 + mt * 16 + (lane & 15), c = kp * 16 + ((lane >> 4) << 3);
                LDSM4(ah2[mt], cvta(SAi(st, 0, r, c)));
                LDSM4(al2[mt], cvta(SAi(st, 1, r, c)));
            }
            int bg = lane >> 3;
            int kr = kp * 16 + ((bg & 1) << 3) + (lane & 7);
#pragma unroll
            for (int nb = 0; nb < 2; nb++) {
                int nc = wn * 32 + nb * 16 + ((bg >> 1) << 3);
                LDSM4T(&b0h[nb * 4], cvta(SB0i(st, 0, kr, nc)));
                LDSM4T(&b0l[nb * 4], cvta(SB0i(st, 1, kr, nc)));
                LDSM4T(&b1h[nb * 4], cvta(SB1i(st, 0, kr, nc)));
                LDSM4T(&b1l[nb * 4], cvta(SB1i(st, 1, kr, nc)));
            }
#pragma unroll
            for (int mt = 0; mt < 2; mt++)
#pragma unroll
                for (int nt = 0; nt < 4; nt++) {
                    int f = (nt >> 1) * 4 + ((nt & 1) << 1);
                    MMA16(ag[mt][nt], ah2[mt], b0h[f], b0h[f + 1]);
                    MMA16(ag[mt][nt], ah2[mt], b0l[f], b0l[f + 1]);
                    MMA16(ag[mt][nt], al2[mt], b0h[f], b0h[f + 1]);
                    MMA16(au[mt][nt], ah2[mt], b1h[f], b1h[f + 1]);
                    MMA16(au[mt][nt], ah2[mt], b1l[f], b1l[f + 1]);
                    MMA16(au[mt][nt], al2[mt], b1h[f], b1h[f + 1]);
                }
        }
        __syncthreads();
    }
#pragma unroll
    for (int mt = 0; mt < 2; mt++)
#pragma unroll
        for (int nt = 0; nt < 4; nt++)
#pragma unroll
            for (int e = 0; e < 4; e++) {
                int r0 = bm + wm * 32 + mt * 16 + (lane >> 2) + (e >= 2 ? 8 : 0);
                int c0 = bn + wn * 32 + nt * 8 + 2 * (lane & 3) + (e & 1);
                float x = ag[mt][nt][e];
                float t = tanhf(0.7978845608028654f * (x + 0.044715f * x * x * x));
                splitstore(Oh, Ol, (size_t)r0 * N + c0, 0.5f * x * (1.f + t) * au[mt][nt][e]);
            }
#undef SAi
#undef SB0i
#undef SB1i
}

// ============ flash attention: softcap, no-max softmax, full P split ============
__global__ void __launch_bounds__(256) k_flash(int is_local) {
    extern __shared__ char dsm[];
    bf16* sm = (bf16*)dsm;
    bf16 *sQh = sm, *sQl = sm + 4608, *sKh = sm + 2 * 4608, *sKl = sm + 3 * 4608,
         *sVh = sm + 4 * 4608, *sVl = sm + 5 * 4608, *sPh = sm + 6 * 4608, *sPl = sm + 7 * 4608;
    float* srs = (float*)(sm + 8 * 4608);
    int h = blockIdx.y, g = h / GSc, t0 = blockIdx.x * 64;
    int tid = threadIdx.x, lane = tid & 31, warp = tid >> 5;
    int wm = warp & 1, wn = warp >> 1;
    const bf16* Qh_ = bq_h + ((size_t)h * Tc + t0) * HDc;
    const bf16* Ql_ = bq_l + ((size_t)h * Tc + t0) * HDc;
#pragma unroll
    for (int i = 0; i < 2; i++) {
        int c = tid + i * 256, r = c >> 3, cc = (c & 7) << 3;
        CPA16(cvta(sQh + r * 72 + cc), Qh_ + r * HDc + cc);
        CPA16(cvta(sQl + r * 72 + cc), Ql_ + r * HDc + cc);
    }
    CPCOMMIT();
    if (tid < 64) srs[tid] = 0.f;
    float ao[2][2][4] = {};
    float rs_[2][2] = {};
    int s_lo = is_local ? ((CACHEc + t0 - WINc + 1) >> 6) : 0;
    int s_hi = (CACHEc + t0 + 63) >> 6;
    CPWAIT(0);
    __syncthreads();
    for (int stile = s_lo; stile <= s_hi; stile++) {
        int s0 = stile << 6;
        const bf16* Kh_ = bk_h + ((size_t)g * Sc + s0) * HDc;
        const bf16* Kl_ = bk_l + ((size_t)g * Sc + s0) * HDc;
        const bf16* Vh_ = bv_h + (size_t)g * HDc * Sc + s0;
        const bf16* Vl_ = bv_l + (size_t)g * HDc * Sc + s0;
#pragma unroll
        for (int i = 0; i < 2; i++) {
            int c = tid + i * 256, r = c >> 3, cc = (c & 7) << 3;
            CPA16(cvta(sKh + r * 72 + cc), Kh_ + r * HDc + cc);
            CPA16(cvta(sKl + r * 72 + cc), Kl_ + r * HDc + cc);
            CPA16(cvta(sVh + r * 72 + cc), Vh_ + (size_t)r * Sc + cc);
            CPA16(cvta(sVl + r * 72 + cc), Vl_ + (size_t)r * Sc + cc);
        }
        CPCOMMIT(); CPWAIT(0);
        __syncthreads();
        float sc_[2][2][4] = {};
#pragma unroll
        for (int kp = 0; kp < 4; kp++) {
            uint32_t ah2[2][4], al2[2][4], bh2[4], bl2[4];
#pragma unroll
            for (int mt = 0; mt < 2; mt++) {
                int r = wm * 32 + mt * 16 + (lane & 15), c = kp * 16 + ((lane >> 4) << 3);
                LDSM4(ah2[mt], cvta(sQh + r * 72 + c));
                LDSM4(al2[mt], cvta(sQl + r * 72 + c));
            }
            int bg = lane >> 3;
            int nr = wn * 16 + ((bg >> 1) << 3) + (lane & 7);
            int kc = kp * 16 + ((bg & 1) << 3);
            LDSM4(bh2, cvta(sKh + nr * 72 + kc));
            LDSM4(bl2, cvta(sKl + nr * 72 + kc));
#pragma unroll
            for (int mt = 0; mt < 2; mt++)
#pragma unroll
                for (int nt = 0; nt < 2; nt++) {
                    MMA16(sc_[mt][nt], ah2[mt], bh2[2 * nt], bh2[2 * nt + 1]);
                    MMA16(sc_[mt][nt], ah2[mt], bl2[2 * nt], bl2[2 * nt + 1]);
                    MMA16(sc_[mt][nt], al2[mt], bh2[2 * nt], bh2[2 * nt + 1]);
                }
        }
#pragma unroll
        for (int mt = 0; mt < 2; mt++)
#pragma unroll
            for (int nt = 0; nt < 2; nt++)
#pragma unroll
                for (int e = 0; e < 4; e++) {
                    int tl = wm * 32 + mt * 16 + (lane >> 2) + (e >= 2 ? 8 : 0);
                    int sl = wn * 16 + nt * 8 + 2 * (lane & 3) + (e & 1);
                    int sp = s0 + sl, qpos = CACHEc + t0 + tl;
                    float v = tanhf(sc_[mt][nt][e] * 0.0025f) * 50.f;
                    bool ok = (sp <= qpos) && (!is_local || sp > qpos - WINc);
                    float p = ok ? __expf(v) : 0.f;
                    rs_[mt][e >= 2 ? 1 : 0] += p;
                    bf16 ph = __float2bfloat16(p);
                    sPh[tl * 72 + sl] = ph;
                    sPl[tl * 72 + sl] = __float2bfloat16(p - __bfloat162float(ph));
                }
        __syncthreads();
#pragma unroll
        for (int kp = 0; kp < 4; kp++) {
            uint32_t ah2[2][4], al2[2][4], bh2[4], bl2[4];
#pragma unroll
            for (int mt = 0; mt < 2; mt++) {
                int r = wm * 32 + mt * 16 + (lane & 15), c = kp * 16 + ((lane >> 4) << 3);
                LDSM4(ah2[mt], cvta(sPh + r * 72 + c));
                LDSM4(al2[mt], cvta(sPl + r * 72 + c));
            }
            int bg = lane >> 3;
            int nr = wn * 16 + ((bg >> 1) << 3) + (lane & 7);
            int kc = kp * 16 + ((bg & 1) << 3);
            LDSM4(bh2, cvta(sVh + nr * 72 + kc));
            LDSM4(bl2, cvta(sVl + nr * 72 + kc));
#pragma unroll
            for (int mt = 0; mt < 2; mt++)
#pragma unroll
                for (int nt = 0; nt < 2; nt++) {
                    MMA16(ao[mt][nt], ah2[mt], bh2[2 * nt], bh2[2 * nt + 1]);
                    MMA16(ao[mt][nt], ah2[mt], bl2[2 * nt], bl2[2 * nt + 1]);
                    MMA16(ao[mt][nt], al2[mt], bh2[2 * nt], bh2[2 * nt + 1]);
                }
        }
        __syncthreads();
    }
#pragma unroll
    for (int mt = 0; mt < 2; mt++) {
        atomicAdd(&srs[wm * 32 + mt * 16 + (lane >> 2)], rs_[mt][0]);
        atomicAdd(&srs[wm * 32 + mt * 16 + (lane >> 2) + 8], rs_[mt][1]);
    }
    __syncthreads();
#pragma unroll
    for (int mt = 0; mt < 2; mt++)
#pragma unroll
        for (int nt = 0; nt < 2; nt++) {
            int tl = wm * 32 + mt * 16 + (lane >> 2);
            int d = wn * 16 + nt * 8 + 2 * (lane & 3);
            float i0 = 1.f / srs[tl], i1 = 1.f / srs[tl + 8];
            size_t b0 = (size_t)(t0 + tl) * Dc + h * HDc + d;
            size_t b1 = (size_t)(t0 + tl + 8) * Dc + h * HDc + d;
            splitstore(bat_h, bat_l, b0, ao[mt][nt][0] * i0);
            splitstore(bat_h, bat_l, b0 + 1, ao[mt][nt][1] * i0);
            splitstore(bat_h, bat_l, b1, ao[mt][nt][2] * i1);
            splitstore(bat_h, bat_l, b1 + 1, ao[mt][nt][3] * i1);
        }
}

// ---------------- host ----------------
extern "C" void kernel_launch(void* const* d_in, const int* in_sizes, int n_in,
                              void* d_out, int out_size) {
    const float *emb = 0, *kvk = 0, *kvv = 0, *pre_attn = 0, *wqkv = 0, *qnorm = 0,
                *knorm = 0, *wout = 0, *post_attn = 0, *pre_ff = 0, *wgate = 0,
                *wup = 0, *wdown = 0, *post_ff = 0, *finalw = 0, *wlm = 0,
                *cosg = 0, *sing = 0, *cosl = 0, *sinl = 0;
    int kv_n = 0, a = 0, b = 0, c = 0, d = 0;
    for (int i = 0; i < n_in; i++) {
        const float* p = (const float*)d_in[i];
        int s = in_sizes[i];
        if (s == 393216) emb = p;
        else if (s == 10223616) { if (kv_n++ == 0) kvk = p; else kvv = p; }
        else if (s == 19968) { if (a == 0) pre_attn = p; else if (a == 1) post_attn = p; else if (a == 2) pre_ff = p; else post_ff = p; a++; }
        else if (s == SZ_WQKV) wqkv = p;
        else if (s == 1664) { if (b++ == 0) qnorm = p; else knorm = p; }
        else if (s == SZ_WOUT) wout = p;
        else if (s == SZ_WFF) { if (c == 0) wgate = p; else if (c == 1) wup = p; else wdown = p; c++; }
        else if (s == 768) finalw = p;
        else if (s == SZ_WLM) wlm = p;
        else if (s == 32768) { if (d == 0) cosg = p; else if (d == 1) sing = p; else if (d == 2) cosl = p; else sinl = p; d++; }
    }
    float *ph, *pqkv, *pt1;
    bf16 *pxh, *pxl, *path, *patl, *pgh, *pgl, *kh, *kl, *vh, *vl;
    bf16 *qkvh, *qkvl, *outh, *outl, *dnh, *dnl, *lmh, *lml, *gth, *gtl, *uph, *upl;
    cudaGetSymbolAddress((void**)&ph, g_h);
    cudaGetSymbolAddress((void**)&pqkv, g_qkv);
    cudaGetSymbolAddress((void**)&pt1, g_t1);
    cudaGetSymbolAddress((void**)&pxh, bx_h); cudaGetSymbolAddress((void**)&pxl, bx_l);
    cudaGetSymbolAddress((void**)&path, bat_h); cudaGetSymbolAddress((void**)&patl, bat_l);
    cudaGetSymbolAddress((void**)&pgh, bgt_h); cudaGetSymbolAddress((void**)&pgl, bgt_l);
    cudaGetSymbolAddress((void**)&kh, bk_h); cudaGetSymbolAddress((void**)&kl, bk_l);
    cudaGetSymbolAddress((void**)&vh, bv_h); cudaGetSymbolAddress((void**)&vl, bv_l);
    cudaGetSymbolAddress((void**)&qkvh, wqkv_h); cudaGetSymbolAddress((void**)&qkvl, wqkv_l);
    cudaGetSymbolAddress((void**)&outh, wout_h); cudaGetSymbolAddress((void**)&outl, wout_l);
    cudaGetSymbolAddress((void**)&gth, wgt_h); cudaGetSymbolAddress((void**)&gtl, wgt_l);
    cudaGetSymbolAddress((void**)&uph, wup_h); cudaGetSymbolAddress((void**)&upl, wup_l);
    cudaGetSymbolAddress((void**)&dnh, wdn_h); cudaGetSymbolAddress((void**)&dnl, wdn_l);
    cudaGetSymbolAddress((void**)&lmh, wlm_h); cudaGetSymbolAddress((void**)&lml, wlm_l);

    const int SM64 = (2 * 2 * 64 * 40 + 2 * 2 * 32 * 72) * 2;
    const int SM128 = (2 * 2 * 128 * 40 + 2 * 2 * 32 * 72) * 2;
    const int SMFF = (2 * 2 * 128 * 40 + 2 * 2 * 2 * 32 * 72) * 2;
    const int SMFL = 8 * 4608 * 2 + 64 * 4;

    cudaFuncSetAttribute(k_mm_t<64, 2>, cudaFuncAttributeMaxDynamicSharedMemorySize, SM64);
    cudaFuncSetAttribute(k_mm_t<128, 4>, cudaFuncAttributeMaxDynamicSharedMemorySize, SM128);
    cudaFuncSetAttribute(k_mmff, cudaFuncAttributeMaxDynamicSharedMemorySize, SMFF);
    cudaFuncSetAttribute(k_flash, cudaFuncAttributeMaxDynamicSharedMemorySize, SMFL);

    k_split4<<<SZ_WQKV / 4 / 256, 256>>>(wqkv, qkvh, qkvl, SZ_WQKV / 4);
    k_split4<<<SZ_WOUT / 4 / 256, 256>>>(wout, outh, outl, SZ_WOUT / 4);
    k_split4<<<SZ_WFF / 4 / 256, 256>>>(wgate, gth, gtl, SZ_WFF / 4);
    k_split4<<<SZ_WFF / 4 / 256, 256>>>(wup, uph, upl, SZ_WFF / 4);
    k_split4<<<SZ_WFF / 4 / 256, 256>>>(wdown, dnh, dnl, SZ_WFF / 4);
    k_split4<<<SZ_WLM / 4 / 256, 256>>>(wlm, lmh, lml, SZ_WLM / 4);

    k_init<<<Tc, 256>>>(emb, pre_attn, ph, pxh, pxl);

    for (int i = 0; i < Lc; i++) {
        int is_local = ((i + 1) % 6 == 0) ? 1 : 0;
        const float* cs = is_local ? cosl : cosg;
        const float* sn = is_local ? sinl : sing;
        k_convkv<<<768, 256>>>(kvk + (size_t)i * 393216, kvv + (size_t)i * 393216,
                               kh, kl, vh, vl);
        k_mm_t<64, 2><<<dim3(QKVW / 64, Tc / 64), 256, SM64>>>(
            pxh, pxl, qkvh + (size_t)i * Dc * QKVW, qkvl + (size_t)i * Dc * QKVW,
            pqkv, QKVW, Dc);
        k_qkprep<<<dim3(Tc, NGc), HDc>>>(pqkv, qnorm + i * HDc, knorm + i * HDc, cs, sn);
        k_flash<<<dim3(Tc / 64, NHc), 256, SMFL>>>(is_local);
        k_mm_t<64, 2><<<dim3(Dc / 64, Tc / 64), 256, SM64>>>(
            path, patl, outh + (size_t)i * Dc * Dc, outl + (size_t)i * Dc * Dc,
            pt1, Dc, Dc);
        k_fuse<<<Tc, 256>>>(ph, pt1, post_attn + i * Dc, pre_ff + i * Dc, pxh, pxl);
        k_mmff<<<dim3(FFc / 64, Tc / 128), 256, SMFF>>>(
            pxh, pxl,
            gth + (size_t)i * Dc * FFc, gtl + (size_t)i * Dc * FFc,
            uph + (size_t)i * Dc * FFc, upl + (size_t)i * Dc * FFc,
            pgh, pgl);
        k_mm_t<64, 2><<<dim3(Dc / 64, Tc / 64), 256, SM64>>>(
            pgh, pgl, dnh + (size_t)i * FFc * Dc, dnl + (size_t)i * FFc * Dc,
            pt1, Dc, FFc);
        const float* wpre = (i + 1 < Lc) ? pre_attn + (i + 1) * Dc : finalw;
        k_fuse<<<Tc, 256>>>(ph, pt1, post_ff + i * Dc, wpre, pxh, pxl);
    }
    k_mm_t<128, 4><<<dim3(Vocab / 64, Tc / 128), 256, SM128>>>(
        pxh, pxl, lmh, lml, (float*)d_out, Vocab, Dc);
}

// round 8
// speedup vs baseline: 1.0816x; 1.0816x over previous
#include <cuda_runtime.h>
#include <cuda_bf16.h>
#include <math.h>
#include <stdint.h>

#define Lc 26
#define Tc 512
#define Dc 768
#define NHc 12
#define NGc 4
#define GSc 3
#define HDc 64
#define FFc 2048
#define CACHEc 1536
#define Sc 2048
#define Vocab 32000
#define WINc 512
#define QKVW 1280
typedef __nv_bfloat16 bf16;

#define SZ_WQKV 25559040
#define SZ_WOUT 15335424
#define SZ_WFF  40894464
#define SZ_WLM  24576000

// ---------------- scratch ----------------
__device__ float g_h[Tc * Dc];
__device__ float g_qkv[Tc * QKVW];
__device__ float g_t1[Tc * Dc];
__device__ bf16 bx_h[Tc * Dc], bx_l[Tc * Dc];
__device__ bf16 bat_h[Tc * Dc], bat_l[Tc * Dc];
__device__ bf16 bgt_h[Tc * FFc], bgt_l[Tc * FFc];
__device__ bf16 bq_h[NHc * Tc * HDc], bq_l[NHc * Tc * HDc];
__device__ bf16 bk_h[NGc * Sc * HDc], bk_l[NGc * Sc * HDc];
__device__ bf16 bv_h[NGc * HDc * Sc], bv_l[NGc * HDc * Sc];
__device__ bf16 wqkv_h[SZ_WQKV], wqkv_l[SZ_WQKV];
__device__ bf16 wout_h[SZ_WOUT], wout_l[SZ_WOUT];
__device__ bf16 wgt_h[SZ_WFF], wgt_l[SZ_WFF];
__device__ bf16 wup_h[SZ_WFF], wup_l[SZ_WFF];
__device__ bf16 wdn_h[SZ_WFF], wdn_l[SZ_WFF];
__device__ bf16 wlm_h[SZ_WLM], wlm_l[SZ_WLM];

// ---------------- asm helpers ----------------
__device__ __forceinline__ uint32_t cvta(const void* p) {
    return (uint32_t)__cvta_generic_to_shared(p);
}
#define LDSM4(r, a) asm volatile( \
    "ldmatrix.sync.aligned.m8n8.x4.shared.b16 {%0,%1,%2,%3},[%4];\n" \
    : "=r"((r)[0]), "=r"((r)[1]), "=r"((r)[2]), "=r"((r)[3]) : "r"(a))
#define LDSM4T(r, a) asm volatile( \
    "ldmatrix.sync.aligned.m8n8.x4.trans.shared.b16 {%0,%1,%2,%3},[%4];\n" \
    : "=r"((r)[0]), "=r"((r)[1]), "=r"((r)[2]), "=r"((r)[3]) : "r"(a))
#define MMA16(c, a, b0, b1) asm volatile( \
    "mma.sync.aligned.m16n8k16.row.col.f32.bf16.bf16.f32 " \
    "{%0,%1,%2,%3},{%4,%5,%6,%7},{%8,%9},{%0,%1,%2,%3};\n" \
    : "+f"((c)[0]), "+f"((c)[1]), "+f"((c)[2]), "+f"((c)[3]) \
    : "r"((a)[0]), "r"((a)[1]), "r"((a)[2]), "r"((a)[3]), "r"(b0), "r"(b1))
#define CPA16(d, s) asm volatile("cp.async.cg.shared.global [%0],[%1],16;\n" :: "r"(d), "l"(s))
#define CPCOMMIT() asm volatile("cp.async.commit_group;\n")
#define CPWAIT(n) asm volatile("cp.async.wait_group %0;\n" :: "n"(n))

__device__ __forceinline__ void splitstore(bf16* ph, bf16* pl, size_t i, float v) {
    bf16 h = __float2bfloat16(v);
    ph[i] = h;
    pl[i] = __float2bfloat16(v - __bfloat162float(h));
}

// vectorized: split float4 -> 8B hi + 8B lo
__device__ __forceinline__ void split4v(float4 v, uint2& hi, uint2& lo) {
    __nv_bfloat162 h0, h1, l0, l1;
    h0.x = __float2bfloat16(v.x); h0.y = __float2bfloat16(v.y);
    h1.x = __float2bfloat16(v.z); h1.y = __float2bfloat16(v.w);
    l0.x = __float2bfloat16(v.x - __bfloat162float(h0.x));
    l0.y = __float2bfloat16(v.y - __bfloat162float(h0.y));
    l1.x = __float2bfloat16(v.z - __bfloat162float(h1.x));
    l1.y = __float2bfloat16(v.w - __bfloat162float(h1.y));
    hi.x = *(uint32_t*)&h0; hi.y = *(uint32_t*)&h1;
    lo.x = *(uint32_t*)&l0; lo.y = *(uint32_t*)&l1;
}

__device__ __forceinline__ float blockReduceSum(float v) {
    __shared__ float sh[8];
    __syncthreads();
    int lane = threadIdx.x & 31, w = threadIdx.x >> 5;
#pragma unroll
    for (int o = 16; o; o >>= 1) v += __shfl_down_sync(0xffffffffu, v, o);
    if (lane == 0) sh[w] = v;
    __syncthreads();
    int nw = blockDim.x >> 5;
    if (w == 0) {
        v = (lane < nw) ? sh[lane] : 0.f;
#pragma unroll
        for (int o = 4; o; o >>= 1) v += __shfl_down_sync(0xffffffffu, v, o);
        if (lane == 0) sh[0] = v;
    }
    __syncthreads();
    return sh[0];
}

// ---------------- elementwise ----------------
__global__ void k_split4(const float* __restrict__ s, bf16* __restrict__ hi,
                         bf16* __restrict__ lo, int n4) {
    int i = blockIdx.x * blockDim.x + threadIdx.x;
    if (i >= n4) return;
    float4 v = ((const float4*)s)[i];
    uint2 h, l;
    split4v(v, h, l);
    ((uint2*)hi)[i] = h;
    ((uint2*)lo)[i] = l;
}

__global__ void k_init(const float* __restrict__ e, const float* __restrict__ w,
                       float* __restrict__ h, bf16* __restrict__ oh, bf16* __restrict__ ol) {
    int row = blockIdx.x;
    const float* x = e + row * Dc;
    float ss = 0.f;
    for (int d = threadIdx.x; d < Dc; d += blockDim.x) { float v = x[d]; ss += v * v; }
    float rs = rsqrtf(blockReduceSum(ss) / Dc + 1e-6f);
    for (int d = threadIdx.x; d < Dc; d += blockDim.x) {
        float v = x[d];
        h[row * Dc + d] = v;
        splitstore(oh, ol, (size_t)row * Dc + d, v * rs * (1.f + w[d]));
    }
}

__global__ void k_fuse(float* __restrict__ h, const float* __restrict__ t1,
                       const float* __restrict__ wpost, const float* __restrict__ wpre,
                       bf16* __restrict__ oh, bf16* __restrict__ ol) {
    int row = blockIdx.x;
    const float* x = t1 + row * Dc;
    float ss = 0.f;
    for (int d = threadIdx.x; d < Dc; d += blockDim.x) { float v = x[d]; ss += v * v; }
    float rs = rsqrtf(blockReduceSum(ss) / Dc + 1e-6f);
    float ss2 = 0.f;
    for (int d = threadIdx.x; d < Dc; d += blockDim.x) {
        float hv = h[row * Dc + d] + x[d] * rs * (1.f + wpost[d]);
        h[row * Dc + d] = hv;
        ss2 += hv * hv;
    }
    float rs2 = rsqrtf(blockReduceSum(ss2) / Dc + 1e-6f);
    for (int d = threadIdx.x; d < Dc; d += blockDim.x)
        splitstore(oh, ol, (size_t)row * Dc + d, h[row * Dc + d] * rs2 * (1.f + wpre[d]));
}

__global__ void k_convkv(const float* __restrict__ ks, const float* __restrict__ vs,
                         bf16* __restrict__ kh, bf16* __restrict__ kl,
                         bf16* __restrict__ vh, bf16* __restrict__ vl) {
    int idx = blockIdx.x * blockDim.x + threadIdx.x;
    if (idx < 98304) {
        int i4 = idx * 4;
        int g = i4 / (CACHEc * HDc), r = i4 - g * (CACHEc * HDc);
        size_t dst = (size_t)g * Sc * HDc + r;
        float4 v = ((const float4*)ks)[idx];
        uint2 h, l;
        split4v(v, h, l);
        *(uint2*)(kh + dst) = h;
        *(uint2*)(kl + dst) = l;
    } else if (idx < 196608) {
        int j4 = (idx - 98304) * 4;
        int row = j4 / CACHEc, c = j4 - row * CACHEc;
        size_t dst = (size_t)row * Sc + c;
        float4 v = ((const float4*)vs)[idx - 98304];
        uint2 h, l;
        split4v(v, h, l);
        *(uint2*)(vh + dst) = h;
        *(uint2*)(vl + dst) = l;
    }
}

__global__ void k_qkprep(const float* __restrict__ qkv,
                         const float* __restrict__ qw, const float* __restrict__ kw,
                         const float* __restrict__ cos_, const float* __restrict__ sin_) {
    int t = blockIdx.x, g = blockIdx.y, d = threadIdx.x;
    const float* base = qkv + ((t * NGc + g) * (GSc + 2)) * HDc;
    __shared__ float sh[HDc];
    __shared__ float r2[2];
    float c = cos_[t * HDc + d], s = sin_[t * HDc + d];
#pragma unroll
    for (int j = 0; j <= GSc; j++) {
        float v = base[j * HDc + d];
        float sq = v * v;
#pragma unroll
        for (int o = 16; o; o >>= 1) sq += __shfl_down_sync(0xffffffffu, sq, o);
        if ((d & 31) == 0) r2[d >> 5] = sq;
        __syncthreads();
        float rs = rsqrtf((r2[0] + r2[1]) * (1.f / HDc) + 1e-6f);
        const float* wgt = (j < GSc) ? qw : kw;
        float nv = v * rs * (1.f + wgt[d]);
        sh[d] = nv;
        __syncthreads();
        float rot = (d < 32) ? -sh[d + 32] : sh[d - 32];
        float outv = nv * c + rot * s;
        if (j < GSc) splitstore(bq_h, bq_l, ((size_t)(g * GSc + j) * Tc + t) * HDc + d, outv);
        else splitstore(bk_h, bk_l, ((size_t)g * Sc + CACHEc + t) * HDc + d, outv);
        __syncthreads();
    }
    splitstore(bv_h, bv_l, (size_t)(g * HDc + d) * Sc + CACHEc + t, base[(GSc + 1) * HDc + d]);
}

// ============ templated GEMM: BM x 64 tile, BK=32, 256 thr ============
template <int BM, int WMW>
__global__ void __launch_bounds__(256) k_mm_t(const bf16* __restrict__ Ah,
                                              const bf16* __restrict__ Al,
                                              const bf16* __restrict__ Bh,
                                              const bf16* __restrict__ Bl,
                                              float* __restrict__ C, int N, int K) {
    constexpr int WNW = 8 / WMW;
    constexpr int WROWS = BM / WMW;
    constexpr int WCOLS = 64 / WNW;
    constexpr int N8 = WCOLS / 8;
    constexpr int NB = WCOLS / 16;
    constexpr int AJ = BM / 64;
    extern __shared__ char dsm[];
    bf16* sA = (bf16*)dsm;
    bf16* sB = (bf16*)(dsm + 2 * 2 * BM * 40 * 2);
#define SAi(st, p, r, c) (sA + ((((st)*2 + (p)) * BM + (r)) * 40 + (c)))
#define SBi(st, p, r, c) (sB + ((((st)*2 + (p)) * 32 + (r)) * 72 + (c)))
    int tid = threadIdx.x, lane = tid & 31, warp = tid >> 5;
    int wm = warp % WMW, wn = warp / WMW;
    int bm = blockIdx.y * BM, bn = blockIdx.x * 64;
    int nIt = K >> 5;
    int br = tid >> 3, bc = (tid & 7) << 3;
    const bf16* pBh = Bh + (size_t)br * N + bn + bc;
    const bf16* pBl = Bl + (size_t)br * N + bn + bc;
    float acc[2][N8][4] = {};
#pragma unroll
    for (int j = 0; j < AJ; j++) {
        int id = tid + j * 256, r = id >> 2, c = (id & 3) << 3;
        CPA16(cvta(SAi(0, 0, r, c)), Ah + (size_t)(bm + r) * K + c);
        CPA16(cvta(SAi(0, 1, r, c)), Al + (size_t)(bm + r) * K + c);
    }
    CPA16(cvta(SBi(0, 0, br, bc)), pBh);
    CPA16(cvta(SBi(0, 1, br, bc)), pBl);
    CPCOMMIT();
    for (int it = 0; it < nIt; it++) {
        int st = it & 1;
        if (it + 1 < nIt) {
            int k0 = (it + 1) << 5;
#pragma unroll
            for (int j = 0; j < AJ; j++) {
                int id = tid + j * 256, r = id >> 2, c = (id & 3) << 3;
                CPA16(cvta(SAi(st ^ 1, 0, r, c)), Ah + (size_t)(bm + r) * K + k0 + c);
                CPA16(cvta(SAi(st ^ 1, 1, r, c)), Al + (size_t)(bm + r) * K + k0 + c);
            }
            CPA16(cvta(SBi(st ^ 1, 0, br, bc)), pBh + (size_t)k0 * N);
            CPA16(cvta(SBi(st ^ 1, 1, br, bc)), pBl + (size_t)k0 * N);
            CPCOMMIT(); CPWAIT(1);
        } else CPWAIT(0);
        __syncthreads();
#pragma unroll
        for (int kp = 0; kp < 2; kp++) {
            uint32_t ah2[2][4], al2[2][4], bh2[4 * NB], bl2[4 * NB];
#pragma unroll
            for (int mt = 0; mt < 2; mt++) {
                int r = wm * WROWS + mt * 16 + (lane & 15), c = kp * 16 + ((lane >> 4) << 3);
                LDSM4(ah2[mt], cvta(SAi(st, 0, r, c)));
                LDSM4(al2[mt], cvta(SAi(st, 1, r, c)));
            }
            int bg = lane >> 3;
            int kr = kp * 16 + ((bg & 1) << 3) + (lane & 7);
#pragma unroll
            for (int nb = 0; nb < NB; nb++) {
                int nc = wn * WCOLS + nb * 16 + ((bg >> 1) << 3);
                LDSM4T(&bh2[nb * 4], cvta(SBi(st, 0, kr, nc)));
                LDSM4T(&bl2[nb * 4], cvta(SBi(st, 1, kr, nc)));
            }
#pragma unroll
            for (int mt = 0; mt < 2; mt++)
#pragma unroll
                for (int nt = 0; nt < N8; nt++) {
                    int f = (nt >> 1) * 4 + ((nt & 1) << 1);
                    MMA16(acc[mt][nt], ah2[mt], bh2[f], bh2[f + 1]);
                    MMA16(acc[mt][nt], ah2[mt], bl2[f], bl2[f + 1]);
                    MMA16(acc[mt][nt], al2[mt], bh2[f], bh2[f + 1]);
                }
        }
        __syncthreads();
    }
#pragma unroll
    for (int mt = 0; mt < 2; mt++)
#pragma unroll
        for (int nt = 0; nt < N8; nt++) {
            int r0 = bm + wm * WROWS + mt * 16 + (lane >> 2);
            int c0 = bn + wn * WCOLS + nt * 8 + 2 * (lane & 3);
            *(float2*)(C + (size_t)r0 * N + c0) = make_float2(acc[mt][nt][0], acc[mt][nt][1]);
            *(float2*)(C + (size_t)(r0 + 8) * N + c0) = make_float2(acc[mt][nt][2], acc[mt][nt][3]);
        }
#undef SAi
#undef SBi
}

// ============ dual GEMM (gate|up) + gelu*mul, BM=128 (4m x 2n warps) ============
__global__ void __launch_bounds__(256) k_mmff(const bf16* __restrict__ Ah,
                                              const bf16* __restrict__ Al,
                                              const bf16* __restrict__ B0h,
                                              const bf16* __restrict__ B0l,
                                              const bf16* __restrict__ B1h,
                                              const bf16* __restrict__ B1l,
                                              bf16* __restrict__ Oh, bf16* __restrict__ Ol) {
    constexpr int BM = 128;
    extern __shared__ char dsm[];
    bf16* sA = (bf16*)dsm;
    bf16* sB0 = (bf16*)(dsm + 2 * 2 * BM * 40 * 2);
    bf16* sB1 = (bf16*)(dsm + 2 * 2 * BM * 40 * 2 + 2 * 2 * 32 * 72 * 2);
#define SAi(st, p, r, c) (sA + ((((st)*2 + (p)) * BM + (r)) * 40 + (c)))
#define SB0i(st, p, r, c) (sB0 + ((((st)*2 + (p)) * 32 + (r)) * 72 + (c)))
#define SB1i(st, p, r, c) (sB1 + ((((st)*2 + (p)) * 32 + (r)) * 72 + (c)))
    const int N = FFc, K = Dc;
    int tid = threadIdx.x, lane = tid & 31, warp = tid >> 5;
    int wm = warp & 3, wn = warp >> 2;
    int bm = blockIdx.y * BM, bn = blockIdx.x * 64;
    int br = tid >> 3, bc = (tid & 7) << 3;
    size_t boff = (size_t)br * N + bn + bc;
    float ag[2][4][4] = {}, au[2][4][4] = {};
#pragma unroll
    for (int j = 0; j < 2; j++) {
        int id = tid + j * 256, r = id >> 2, c = (id & 3) << 3;
        CPA16(cvta(SAi(0, 0, r, c)), Ah + (size_t)(bm + r) * K + c);
        CPA16(cvta(SAi(0, 1, r, c)), Al + (size_t)(bm + r) * K + c);
    }
    CPA16(cvta(SB0i(0, 0, br, bc)), B0h + boff); CPA16(cvta(SB0i(0, 1, br, bc)), B0l + boff);
    CPA16(cvta(SB1i(0, 0, br, bc)), B1h + boff); CPA16(cvta(SB1i(0, 1, br, bc)), B1l + boff);
    CPCOMMIT();
    for (int it = 0; it < (K >> 5); it++) {
        int st = it & 1;
        if (it + 1 < (K >> 5)) {
            int k0 = (it + 1) << 5;
#pragma unroll
            for (int j = 0; j < 2; j++) {
                int id = tid + j * 256, r = id >> 2, c = (id & 3) << 3;
                CPA16(cvta(SAi(st ^ 1, 0, r, c)), Ah + (size_t)(bm + r) * K + k0 + c);
                CPA16(cvta(SAi(st ^ 1, 1, r, c)), Al + (size_t)(bm + r) * K + k0 + c);
            }
            CPA16(cvta(SB0i(st ^ 1, 0, br, bc)), B0h + boff + (size_t)k0 * N);
            CPA16(cvta(SB0i(st ^ 1, 1, br, bc)), B0l + boff + (size_t)k0 * N);
            CPA16(cvta(SB1i(st ^ 1, 0, br, bc)), B1h + boff + (size_t)k0 * N);
            CPA16(cvta(SB1i(st ^ 1, 1, br, bc)), B1l + boff + (size_t)k0 * N);
            CPCOMMIT(); CPWAIT(1);
        } else CPWAIT(0);
        __syncthreads();
#pragma unroll
        for (int kp = 0; kp < 2; kp++) {
            uint32_t ah2[2][4], al2[2][4], b0h[8], b0l[8], b1h[8], b1l[8];
#pragma unroll
            for (int mt = 0; mt < 2; mt++) {
                int r = wm * 32 + mt * 16 + (lane & 15), c = kp * 16 + ((lane >> 4) << 3);
                LDSM4(ah2[mt], cvta(SAi(st, 0, r, c)));
                LDSM4(al2[mt], cvta(SAi(st, 1, r, c)));
            }
            int bg = lane >> 3;
            int kr = kp * 16 + ((bg & 1) << 3) + (lane & 7);
#pragma unroll
            for (int nb = 0; nb < 2; nb++) {
                int nc = wn * 32 + nb * 16 + ((bg >> 1) << 3);
                LDSM4T(&b0h[nb * 4], cvta(SB0i(st, 0, kr, nc)));
                LDSM4T(&b0l[nb * 4], cvta(SB0i(st, 1, kr, nc)));
                LDSM4T(&b1h[nb * 4], cvta(SB1i(st, 0, kr, nc)));
                LDSM4T(&b1l[nb * 4], cvta(SB1i(st, 1, kr, nc)));
            }
#pragma unroll
            for (int mt = 0; mt < 2; mt++)
#pragma unroll
                for (int nt = 0; nt < 4; nt++) {
                    int f = (nt >> 1) * 4 + ((nt & 1) << 1);
                    MMA16(ag[mt][nt], ah2[mt], b0h[f], b0h[f + 1]);
                    MMA16(ag[mt][nt], ah2[mt], b0l[f], b0l[f + 1]);
                    MMA16(ag[mt][nt], al2[mt], b0h[f], b0h[f + 1]);
                    MMA16(au[mt][nt], ah2[mt], b1h[f], b1h[f + 1]);
                    MMA16(au[mt][nt], ah2[mt], b1l[f], b1l[f + 1]);
                    MMA16(au[mt][nt], al2[mt], b1h[f], b1h[f + 1]);
                }
        }
        __syncthreads();
    }
#pragma unroll
    for (int mt = 0; mt < 2; mt++)
#pragma unroll
        for (int nt = 0; nt < 4; nt++)
#pragma unroll
            for (int e = 0; e < 4; e++) {
                int r0 = bm + wm * 32 + mt * 16 + (lane >> 2) + (e >= 2 ? 8 : 0);
                int c0 = bn + wn * 32 + nt * 8 + 2 * (lane & 3) + (e & 1);
                float x = ag[mt][nt][e];
                float t = tanhf(0.7978845608028654f * (x + 0.044715f * x * x * x));
                splitstore(Oh, Ol, (size_t)r0 * N + c0, 0.5f * x * (1.f + t) * au[mt][nt][e]);
            }
#undef SAi
#undef SB0i
#undef SB1i
}

// ============ flash attention: softcap, no-max softmax, 2-stage KV pipeline ============
__global__ void __launch_bounds__(256) k_flash(int is_local) {
    extern __shared__ char dsm[];
    bf16* sm = (bf16*)dsm;
    bf16* sQh = sm;
    bf16* sQl = sm + 4608;
    bf16* sKV[2][4];  // [stage][Kh,Kl,Vh,Vl]
    sKV[0][0] = sm + 2 * 4608; sKV[0][1] = sm + 3 * 4608;
    sKV[0][2] = sm + 4 * 4608; sKV[0][3] = sm + 5 * 4608;
    sKV[1][0] = sm + 6 * 4608; sKV[1][1] = sm + 7 * 4608;
    sKV[1][2] = sm + 8 * 4608; sKV[1][3] = sm + 9 * 4608;
    bf16* sPh = sm + 10 * 4608;
    bf16* sPl = sm + 11 * 4608;
    float* srs = (float*)(sm + 12 * 4608);
    int h = blockIdx.y, g = h / GSc, t0 = blockIdx.x * 64;
    int tid = threadIdx.x, lane = tid & 31, warp = tid >> 5;
    int wm = warp & 1, wn = warp >> 1;
    const bf16* Qh_ = bq_h + ((size_t)h * Tc + t0) * HDc;
    const bf16* Ql_ = bq_l + ((size_t)h * Tc + t0) * HDc;
#pragma unroll
    for (int i = 0; i < 2; i++) {
        int c = tid + i * 256, r = c >> 3, cc = (c & 7) << 3;
        CPA16(cvta(sQh + r * 72 + cc), Qh_ + r * HDc + cc);
        CPA16(cvta(sQl + r * 72 + cc), Ql_ + r * HDc + cc);
    }
    if (tid < 64) srs[tid] = 0.f;
    float ao[2][2][4] = {};
    float rs_[2][2] = {};
    int s_lo = is_local ? ((CACHEc + t0 - WINc + 1) >> 6) : 0;
    int s_hi = (CACHEc + t0 + 63) >> 6;

    auto loadkv = [&](int s0, int st) {
        const bf16* Kh_ = bk_h + ((size_t)g * Sc + s0) * HDc;
        const bf16* Kl_ = bk_l + ((size_t)g * Sc + s0) * HDc;
        const bf16* Vh_ = bv_h + (size_t)g * HDc * Sc + s0;
        const bf16* Vl_ = bv_l + (size_t)g * HDc * Sc + s0;
#pragma unroll
        for (int i = 0; i < 2; i++) {
            int c = tid + i * 256, r = c >> 3, cc = (c & 7) << 3;
            CPA16(cvta(sKV[st][0] + r * 72 + cc), Kh_ + r * HDc + cc);
            CPA16(cvta(sKV[st][1] + r * 72 + cc), Kl_ + r * HDc + cc);
            CPA16(cvta(sKV[st][2] + r * 72 + cc), Vh_ + (size_t)r * Sc + cc);
            CPA16(cvta(sKV[st][3] + r * 72 + cc), Vl_ + (size_t)r * Sc + cc);
        }
    };

    // Q + first tile in one commit group
    loadkv(s_lo << 6, 0);
    CPCOMMIT();

    for (int stile = s_lo; stile <= s_hi; stile++) {
        int st = (stile - s_lo) & 1;
        int s0 = stile << 6;
        if (stile < s_hi) {
            loadkv((stile + 1) << 6, st ^ 1);
            CPCOMMIT();
            CPWAIT(1);
        } else {
            CPWAIT(0);
        }
        __syncthreads();
        bf16 *cKh = sKV[st][0], *cKl = sKV[st][1], *cVh = sKV[st][2], *cVl = sKV[st][3];
        float sc_[2][2][4] = {};
#pragma unroll
        for (int kp = 0; kp < 4; kp++) {
            uint32_t ah2[2][4], al2[2][4], bh2[4], bl2[4];
#pragma unroll
            for (int mt = 0; mt < 2; mt++) {
                int r = wm * 32 + mt * 16 + (lane & 15), c = kp * 16 + ((lane >> 4) << 3);
                LDSM4(ah2[mt], cvta(sQh + r * 72 + c));
                LDSM4(al2[mt], cvta(sQl + r * 72 + c));
            }
            int bg = lane >> 3;
            int nr = wn * 16 + ((bg >> 1) << 3) + (lane & 7);
            int kc = kp * 16 + ((bg & 1) << 3);
            LDSM4(bh2, cvta(cKh + nr * 72 + kc));
            LDSM4(bl2, cvta(cKl + nr * 72 + kc));
#pragma unroll
            for (int mt = 0; mt < 2; mt++)
#pragma unroll
                for (int nt = 0; nt < 2; nt++) {
                    MMA16(sc_[mt][nt], ah2[mt], bh2[2 * nt], bh2[2 * nt + 1]);
                    MMA16(sc_[mt][nt], ah2[mt], bl2[2 * nt], bl2[2 * nt + 1]);
                    MMA16(sc_[mt][nt], al2[mt], bh2[2 * nt], bh2[2 * nt + 1]);
                }
        }
#pragma unroll
        for (int mt = 0; mt < 2; mt++)
#pragma unroll
            for (int nt = 0; nt < 2; nt++)
#pragma unroll
                for (int e = 0; e < 4; e++) {
                    int tl = wm * 32 + mt * 16 + (lane >> 2) + (e >= 2 ? 8 : 0);
                    int sl = wn * 16 + nt * 8 + 2 * (lane & 3) + (e & 1);
                    int sp = s0 + sl, qpos = CACHEc + t0 + tl;
                    float v = tanhf(sc_[mt][nt][e] * 0.0025f) * 50.f;
                    bool ok = (sp <= qpos) && (!is_local || sp > qpos - WINc);
                    float p = ok ? __expf(v) : 0.f;
                    rs_[mt][e >= 2 ? 1 : 0] += p;
                    bf16 ph = __float2bfloat16(p);
                    sPh[tl * 72 + sl] = ph;
                    sPl[tl * 72 + sl] = __float2bfloat16(p - __bfloat162float(ph));
                }
        __syncthreads();
#pragma unroll
        for (int kp = 0; kp < 4; kp++) {
            uint32_t ah2[2][4], al2[2][4], bh2[4], bl2[4];
#pragma unroll
            for (int mt = 0; mt < 2; mt++) {
                int r = wm * 32 + mt * 16 + (lane & 15), c = kp * 16 + ((lane >> 4) << 3);
                LDSM4(ah2[mt], cvta(sPh + r * 72 + c));
                LDSM4(al2[mt], cvta(sPl + r * 72 + c));
            }
            int bg = lane >> 3;
            int nr = wn * 16 + ((bg >> 1) << 3) + (lane & 7);
            int kc = kp * 16 + ((bg & 1) << 3);
            LDSM4(bh2, cvta(cVh + nr * 72 + kc));
            LDSM4(bl2, cvta(cVl + nr * 72 + kc));
#pragma unroll
            for (int mt = 0; mt < 2; mt++)
#pragma unroll
                for (int nt = 0; nt < 2; nt++) {
                    MMA16(ao[mt][nt], ah2[mt], bh2[2 * nt], bh2[2 * nt + 1]);
                    MMA16(ao[mt][nt], ah2[mt], bl2[2 * nt], bl2[2 * nt + 1]);
                    MMA16(ao[mt][nt], al2[mt], bh2[2 * nt], bh2[2 * nt + 1]);
                }
        }
        __syncthreads();
    }
#pragma unroll
    for (int mt = 0; mt < 2; mt++) {
        atomicAdd(&srs[wm * 32 + mt * 16 + (lane >> 2)], rs_[mt][0]);
        atomicAdd(&srs[wm * 32 + mt * 16 + (lane >> 2) + 8], rs_[mt][1]);
    }
    __syncthreads();
#pragma unroll
    for (int mt = 0; mt < 2; mt++)
#pragma unroll
        for (int nt = 0; nt < 2; nt++) {
            int tl = wm * 32 + mt * 16 + (lane >> 2);
            int d = wn * 16 + nt * 8 + 2 * (lane & 3);
            float i0 = 1.f / srs[tl], i1 = 1.f / srs[tl + 8];
            size_t b0 = (size_t)(t0 + tl) * Dc + h * HDc + d;
            size_t b1 = (size_t)(t0 + tl + 8) * Dc + h * HDc + d;
            splitstore(bat_h, bat_l, b0, ao[mt][nt][0] * i0);
            splitstore(bat_h, bat_l, b0 + 1, ao[mt][nt][1] * i0);
            splitstore(bat_h, bat_l, b1, ao[mt][nt][2] * i1);
            splitstore(bat_h, bat_l, b1 + 1, ao[mt][nt][3] * i1);
        }
}

// ---------------- host ----------------
extern "C" void kernel_launch(void* const* d_in, const int* in_sizes, int n_in,
                              void* d_out, int out_size) {
    const float *emb = 0, *kvk = 0, *kvv = 0, *pre_attn = 0, *wqkv = 0, *qnorm = 0,
                *knorm = 0, *wout = 0, *post_attn = 0, *pre_ff = 0, *wgate = 0,
                *wup = 0, *wdown = 0, *post_ff = 0, *finalw = 0, *wlm = 0,
                *cosg = 0, *sing = 0, *cosl = 0, *sinl = 0;
    int kv_n = 0, a = 0, b = 0, c = 0, d = 0;
    for (int i = 0; i < n_in; i++) {
        const float* p = (const float*)d_in[i];
        int s = in_sizes[i];
        if (s == 393216) emb = p;
        else if (s == 10223616) { if (kv_n++ == 0) kvk = p; else kvv = p; }
        else if (s == 19968) { if (a == 0) pre_attn = p; else if (a == 1) post_attn = p; else if (a == 2) pre_ff = p; else post_ff = p; a++; }
        else if (s == SZ_WQKV) wqkv = p;
        else if (s == 1664) { if (b++ == 0) qnorm = p; else knorm = p; }
        else if (s == SZ_WOUT) wout = p;
        else if (s == SZ_WFF) { if (c == 0) wgate = p; else if (c == 1) wup = p; else wdown = p; c++; }
        else if (s == 768) finalw = p;
        else if (s == SZ_WLM) wlm = p;
        else if (s == 32768) { if (d == 0) cosg = p; else if (d == 1) sing = p; else if (d == 2) cosl = p; else sinl = p; d++; }
    }
    float *ph, *pqkv, *pt1;
    bf16 *pxh, *pxl, *path, *patl, *pgh, *pgl, *kh, *kl, *vh, *vl;
    bf16 *qkvh, *qkvl, *outh, *outl, *dnh, *dnl, *lmh, *lml, *gth, *gtl, *uph, *upl;
    cudaGetSymbolAddress((void**)&ph, g_h);
    cudaGetSymbolAddress((void**)&pqkv, g_qkv);
    cudaGetSymbolAddress((void**)&pt1, g_t1);
    cudaGetSymbolAddress((void**)&pxh, bx_h); cudaGetSymbolAddress((void**)&pxl, bx_l);
    cudaGetSymbolAddress((void**)&path, bat_h); cudaGetSymbolAddress((void**)&patl, bat_l);
    cudaGetSymbolAddress((void**)&pgh, bgt_h); cudaGetSymbolAddress((void**)&pgl, bgt_l);
    cudaGetSymbolAddress((void**)&kh, bk_h); cudaGetSymbolAddress((void**)&kl, bk_l);
    cudaGetSymbolAddress((void**)&vh, bv_h); cudaGetSymbolAddress((void**)&vl, bv_l);
    cudaGetSymbolAddress((void**)&qkvh, wqkv_h); cudaGetSymbolAddress((void**)&qkvl, wqkv_l);
    cudaGetSymbolAddress((void**)&outh, wout_h); cudaGetSymbolAddress((void**)&outl, wout_l);
    cudaGetSymbolAddress((void**)&gth, wgt_h); cudaGetSymbolAddress((void**)&gtl, wgt_l);
    cudaGetSymbolAddress((void**)&uph, wup_h); cudaGetSymbolAddress((void**)&upl, wup_l);
    cudaGetSymbolAddress((void**)&dnh, wdn_h); cudaGetSymbolAddress((void**)&dnl, wdn_l);
    cudaGetSymbolAddress((void**)&lmh, wlm_h); cudaGetSymbolAddress((void**)&lml, wlm_l);

    const int SM64 = (2 * 2 * 64 * 40 + 2 * 2 * 32 * 72) * 2;
    const int SM128 = (2 * 2 * 128 * 40 + 2 * 2 * 32 * 72) * 2;
    const int SMFF = (2 * 2 * 128 * 40 + 2 * 2 * 2 * 32 * 72) * 2;
    const int SMFL = 12 * 4608 * 2 + 64 * 4;

    cudaFuncSetAttribute(k_mm_t<64, 2>, cudaFuncAttributeMaxDynamicSharedMemorySize, SM64);
    cudaFuncSetAttribute(k_mm_t<128, 4>, cudaFuncAttributeMaxDynamicSharedMemorySize, SM128);
    cudaFuncSetAttribute(k_mmff, cudaFuncAttributeMaxDynamicSharedMemorySize, SMFF);
    cudaFuncSetAttribute(k_flash, cudaFuncAttributeMaxDynamicSharedMemorySize, SMFL);

    // launch order chosen so k_flash is launch #5 (ncu -s 5 -c 1 profiles it)
    k_split4<<<SZ_WQKV / 4 / 256, 256>>>(wqkv, qkvh, qkvl, SZ_WQKV / 4);   // 0
    k_init<<<Tc, 256>>>(emb, pre_attn, ph, pxh, pxl);                      // 1

    for (int i = 0; i < Lc; i++) {
        int is_local = ((i + 1) % 6 == 0) ? 1 : 0;
        const float* cs = is_local ? cosl : cosg;
        const float* sn = is_local ? sinl : sing;
        k_convkv<<<768, 256>>>(kvk + (size_t)i * 393216, kvv + (size_t)i * 393216,
                               kh, kl, vh, vl);                            // 2
        k_mm_t<64, 2><<<dim3(QKVW / 64, Tc / 64), 256, SM64>>>(
            pxh, pxl, qkvh + (size_t)i * Dc * QKVW, qkvl + (size_t)i * Dc * QKVW,
            pqkv, QKVW, Dc);                                               // 3
        k_qkprep<<<dim3(Tc, NGc), HDc>>>(pqkv, qnorm + i * HDc, knorm + i * HDc, cs, sn); // 4
        k_flash<<<dim3(Tc / 64, NHc), 256, SMFL>>>(is_local);              // 5 <- profiled
        if (i == 0) {
            // remaining weight splits: complete (stream-ordered) before first use below
            k_split4<<<SZ_WOUT / 4 / 256, 256>>>(wout, outh, outl, SZ_WOUT / 4);
            k_split4<<<SZ_WFF / 4 / 256, 256>>>(wgate, gth, gtl, SZ_WFF / 4);
            k_split4<<<SZ_WFF / 4 / 256, 256>>>(wup, uph, upl, SZ_WFF / 4);
            k_split4<<<SZ_WFF / 4 / 256, 256>>>(wdown, dnh, dnl, SZ_WFF / 4);
            k_split4<<<SZ_WLM / 4 / 256, 256>>>(wlm, lmh, lml, SZ_WLM / 4);
        }
        k_mm_t<64, 2><<<dim3(Dc / 64, Tc / 64), 256, SM64>>>(
            path, patl, outh + (size_t)i * Dc * Dc, outl + (size_t)i * Dc * Dc,
            pt1, Dc, Dc);
        k_fuse<<<Tc, 256>>>(ph, pt1, post_attn + i * Dc, pre_ff + i * Dc, pxh, pxl);
        k_mmff<<<dim3(FFc / 64, Tc / 128), 256, SMFF>>>(
            pxh, pxl,
            gth + (size_t)i * Dc * FFc, gtl + (size_t)i * Dc * FFc,
            uph + (size_t)i * Dc * FFc, upl + (size_t)i * Dc * FFc,
            pgh, pgl);
        k_mm_t<64, 2><<<dim3(Dc / 64, Tc / 64), 256, SM64>>>(
            pgh, pgl, dnh + (size_t)i * FFc * Dc, dnl + (size_t)i * FFc * Dc,
            pt1, Dc, FFc);
        const float* wpre = (i + 1 < Lc) ? pre_attn + (i + 1) * Dc : finalw;
        k_fuse<<<Tc, 256>>>(ph, pt1, post_ff + i * Dc, wpre, pxh, pxl);
    }
    k_mm_t<128, 4><<<dim3(Vocab / 64, Tc / 128), 256, SM128>>>(
        pxh, pxl, lmh, lml, (float*)d_out, Vocab, Dc);
}

// round 9
// speedup vs baseline: 1.3333x; 1.2327x over previous
#include <cuda_runtime.h>
#include <cuda_bf16.h>
#include <math.h>
#include <stdint.h>

#define Lc 26
#define Tc 512
#define Dc 768
#define NHc 12
#define NGc 4
#define GSc 3
#define HDc 64
#define FFc 2048
#define CACHEc 1536
#define Sc 2048
#define Vocab 32000
#define WINc 512
#define QKVW 1280
typedef __nv_bfloat16 bf16;

#define SZ_WQKV 25559040
#define SZ_WOUT 15335424
#define SZ_WFF  40894464
#define SZ_WLM  24576000
#define KVL (NGc * Sc * HDc)      /* 524288 per layer */
#define NTD (NHc * Tc * HDc)      /* 393216 */

// ---------------- scratch ----------------
__device__ float g_h[Tc * Dc];
__device__ float g_qkv[2 * Tc * QKVW];     // split-K partials
__device__ float g_t1[2 * Tc * Dc];        // split-K partials
__device__ float g_aop[2 * NTD];           // flash split-S partial P*V
__device__ float g_rsp[2 * NHc * Tc];      // flash split-S partial row sums
__device__ bf16 bx_h[Tc * Dc], bx_l[Tc * Dc];
__device__ bf16 bat_h[Tc * Dc], bat_l[Tc * Dc];
__device__ bf16 bgt_h[Tc * FFc], bgt_l[Tc * FFc];
__device__ bf16 bq_h[NTD], bq_l[NTD];
__device__ bf16 bk_h[Lc * KVL], bk_l[Lc * KVL];
__device__ bf16 bv_h[Lc * KVL], bv_l[Lc * KVL];
__device__ bf16 wqkv_h[SZ_WQKV], wqkv_l[SZ_WQKV];
__device__ bf16 wout_h[SZ_WOUT], wout_l[SZ_WOUT];
__device__ bf16 wgt_h[SZ_WFF], wgt_l[SZ_WFF];
__device__ bf16 wup_h[SZ_WFF], wup_l[SZ_WFF];
__device__ bf16 wdn_h[SZ_WFF], wdn_l[SZ_WFF];
__device__ bf16 wlm_h[SZ_WLM], wlm_l[SZ_WLM];

// ---------------- asm helpers ----------------
__device__ __forceinline__ uint32_t cvta(const void* p) {
    return (uint32_t)__cvta_generic_to_shared(p);
}
#define LDSM4(r, a) asm volatile( \
    "ldmatrix.sync.aligned.m8n8.x4.shared.b16 {%0,%1,%2,%3},[%4];\n" \
    : "=r"((r)[0]), "=r"((r)[1]), "=r"((r)[2]), "=r"((r)[3]) : "r"(a))
#define LDSM4T(r, a) asm volatile( \
    "ldmatrix.sync.aligned.m8n8.x4.trans.shared.b16 {%0,%1,%2,%3},[%4];\n" \
    : "=r"((r)[0]), "=r"((r)[1]), "=r"((r)[2]), "=r"((r)[3]) : "r"(a))
#define MMA16(c, a, b0, b1) asm volatile( \
    "mma.sync.aligned.m16n8k16.row.col.f32.bf16.bf16.f32 " \
    "{%0,%1,%2,%3},{%4,%5,%6,%7},{%8,%9},{%0,%1,%2,%3};\n" \
    : "+f"((c)[0]), "+f"((c)[1]), "+f"((c)[2]), "+f"((c)[3]) \
    : "r"((a)[0]), "r"((a)[1]), "r"((a)[2]), "r"((a)[3]), "r"(b0), "r"(b1))
#define CPA16(d, s) asm volatile("cp.async.cg.shared.global [%0],[%1],16;\n" :: "r"(d), "l"(s))
#define CPCOMMIT() asm volatile("cp.async.commit_group;\n")
#define CPWAIT(n) asm volatile("cp.async.wait_group %0;\n" :: "n"(n))

__device__ __forceinline__ void splitstore(bf16* ph, bf16* pl, size_t i, float v) {
    bf16 h = __float2bfloat16(v);
    ph[i] = h;
    pl[i] = __float2bfloat16(v - __bfloat162float(h));
}

__device__ __forceinline__ void split4v(float4 v, uint2& hi, uint2& lo) {
    __nv_bfloat162 h0, h1, l0, l1;
    h0.x = __float2bfloat16(v.x); h0.y = __float2bfloat16(v.y);
    h1.x = __float2bfloat16(v.z); h1.y = __float2bfloat16(v.w);
    l0.x = __float2bfloat16(v.x - __bfloat162float(h0.x));
    l0.y = __float2bfloat16(v.y - __bfloat162float(h0.y));
    l1.x = __float2bfloat16(v.z - __bfloat162float(h1.x));
    l1.y = __float2bfloat16(v.w - __bfloat162float(h1.y));
    hi.x = *(uint32_t*)&h0; hi.y = *(uint32_t*)&h1;
    lo.x = *(uint32_t*)&l0; lo.y = *(uint32_t*)&l1;
}

__device__ __forceinline__ float blockReduceSum(float v) {
    __shared__ float sh[8];
    __syncthreads();
    int lane = threadIdx.x & 31, w = threadIdx.x >> 5;
#pragma unroll
    for (int o = 16; o; o >>= 1) v += __shfl_down_sync(0xffffffffu, v, o);
    if (lane == 0) sh[w] = v;
    __syncthreads();
    int nw = blockDim.x >> 5;
    if (w == 0) {
        v = (lane < nw) ? sh[lane] : 0.f;
#pragma unroll
        for (int o = 4; o; o >>= 1) v += __shfl_down_sync(0xffffffffu, v, o);
        if (lane == 0) sh[0] = v;
    }
    __syncthreads();
    return sh[0];
}

// ---------------- elementwise ----------------
__global__ void k_split4(const float* __restrict__ s, bf16* __restrict__ hi,
                         bf16* __restrict__ lo, int n4) {
    int i = blockIdx.x * blockDim.x + threadIdx.x;
    if (i >= n4) return;
    float4 v = ((const float4*)s)[i];
    uint2 h, l;
    split4v(v, h, l);
    ((uint2*)hi)[i] = h;
    ((uint2*)lo)[i] = l;
}

// all-layer KV conversion
__global__ void k_convall(const float* __restrict__ ks, const float* __restrict__ vs,
                          bf16* __restrict__ kh, bf16* __restrict__ kl,
                          bf16* __restrict__ vh, bf16* __restrict__ vl) {
    int idx = blockIdx.x * blockDim.x + threadIdx.x;
    if (idx >= Lc * 196608) return;
    int layer = idx / 196608;
    int r = idx - layer * 196608;
    const float* ksl = ks + (size_t)layer * 393216;
    const float* vsl = vs + (size_t)layer * 393216;
    size_t kvoff = (size_t)layer * KVL;
    if (r < 98304) {
        int i4 = r * 4;
        int g = i4 / (CACHEc * HDc), rr = i4 - g * (CACHEc * HDc);
        size_t dst = kvoff + (size_t)g * Sc * HDc + rr;
        float4 v = ((const float4*)ksl)[r];
        uint2 h, l;
        split4v(v, h, l);
        *(uint2*)(kh + dst) = h;
        *(uint2*)(kl + dst) = l;
    } else {
        int j4 = (r - 98304) * 4;
        int row = j4 / CACHEc, c = j4 - row * CACHEc;
        size_t dst = kvoff + (size_t)row * Sc + c;
        float4 v = ((const float4*)vsl)[r - 98304];
        uint2 h, l;
        split4v(v, h, l);
        *(uint2*)(vh + dst) = h;
        *(uint2*)(vl + dst) = l;
    }
}

__global__ void k_init(const float* __restrict__ e, const float* __restrict__ w,
                       float* __restrict__ h, bf16* __restrict__ oh, bf16* __restrict__ ol) {
    int row = blockIdx.x;
    const float* x = e + row * Dc;
    float ss = 0.f;
    for (int d = threadIdx.x; d < Dc; d += blockDim.x) { float v = x[d]; ss += v * v; }
    float rs = rsqrtf(blockReduceSum(ss) / Dc + 1e-6f);
    for (int d = threadIdx.x; d < Dc; d += blockDim.x) {
        float v = x[d];
        h[row * Dc + d] = v;
        splitstore(oh, ol, (size_t)row * Dc + d, v * rs * (1.f + w[d]));
    }
}

// h += rmsnorm(t1a+t1b, wpost); out = split(rmsnorm(h, wpre))
__global__ void k_fuse(float* __restrict__ h, const float* __restrict__ t1,
                       const float* __restrict__ wpost, const float* __restrict__ wpre,
                       bf16* __restrict__ oh, bf16* __restrict__ ol) {
    int row = blockIdx.x;
    const float* x0 = t1 + row * Dc;
    const float* x1 = t1 + Tc * Dc + row * Dc;
    float ss = 0.f;
    for (int d = threadIdx.x; d < Dc; d += blockDim.x) {
        float v = x0[d] + x1[d];
        ss += v * v;
    }
    float rs = rsqrtf(blockReduceSum(ss) / Dc + 1e-6f);
    float ss2 = 0.f;
    for (int d = threadIdx.x; d < Dc; d += blockDim.x) {
        float hv = h[row * Dc + d] + (x0[d] + x1[d]) * rs * (1.f + wpost[d]);
        h[row * Dc + d] = hv;
        ss2 += hv * hv;
    }
    float rs2 = rsqrtf(blockReduceSum(ss2) / Dc + 1e-6f);
    for (int d = threadIdx.x; d < Dc; d += blockDim.x)
        splitstore(oh, ol, (size_t)row * Dc + d, h[row * Dc + d] * rs2 * (1.f + wpre[d]));
}

// qkv split-K sum + head rmsnorm + rope + cache append
__global__ void k_qkprep(const float* __restrict__ qkv,
                         const float* __restrict__ qw, const float* __restrict__ kw,
                         const float* __restrict__ cos_, const float* __restrict__ sin_,
                         bf16* __restrict__ kh, bf16* __restrict__ kl,
                         bf16* __restrict__ vh, bf16* __restrict__ vl) {
    int t = blockIdx.x, g = blockIdx.y, d = threadIdx.x;
    size_t boff = ((size_t)(t * NGc + g) * (GSc + 2)) * HDc;
    const float* b0 = qkv + boff;
    const float* b1 = qkv + (size_t)Tc * QKVW + boff;
    __shared__ float sh[HDc];
    __shared__ float r2[2];
    float c = cos_[t * HDc + d], s = sin_[t * HDc + d];
#pragma unroll
    for (int j = 0; j <= GSc; j++) {
        float v = b0[j * HDc + d] + b1[j * HDc + d];
        float sq = v * v;
#pragma unroll
        for (int o = 16; o; o >>= 1) sq += __shfl_down_sync(0xffffffffu, sq, o);
        if ((d & 31) == 0) r2[d >> 5] = sq;
        __syncthreads();
        float rs = rsqrtf((r2[0] + r2[1]) * (1.f / HDc) + 1e-6f);
        const float* wgt = (j < GSc) ? qw : kw;
        float nv = v * rs * (1.f + wgt[d]);
        sh[d] = nv;
        __syncthreads();
        float rot = (d < 32) ? -sh[d + 32] : sh[d - 32];
        float outv = nv * c + rot * s;
        if (j < GSc) splitstore(bq_h, bq_l, ((size_t)(g * GSc + j) * Tc + t) * HDc + d, outv);
        else splitstore(kh, kl, ((size_t)g * Sc + CACHEc + t) * HDc + d, outv);
        __syncthreads();
    }
    float vv = b0[(GSc + 1) * HDc + d] + b1[(GSc + 1) * HDc + d];
    splitstore(vh, vl, (size_t)(g * HDc + d) * Sc + CACHEc + t, vv);
}

// flash combine: o = (a0+a1)/(r0+r1), write bf16 split attn
__global__ void k_fcomb(const float* __restrict__ aop, const float* __restrict__ rsp,
                        bf16* __restrict__ oh, bf16* __restrict__ ol) {
    int i = blockIdx.x * blockDim.x + threadIdx.x;
    if (i >= NTD) return;
    int h = i / (Tc * HDc);
    int rem = i - h * (Tc * HDc);
    int t = rem / HDc, d = rem - (rem / HDc) * HDc;
    float r = rsp[h * Tc + t] + rsp[NHc * Tc + h * Tc + t];
    float o = (aop[i] + aop[NTD + i]) / r;
    splitstore(oh, ol, (size_t)t * Dc + h * HDc + d, o);
}

// ============ templated GEMM: BM x 64 tile, BK=32, split-K via blockIdx.z ============
template <int BM, int WMW>
__global__ void __launch_bounds__(256) k_mm_t(const bf16* __restrict__ Ah,
                                              const bf16* __restrict__ Al,
                                              const bf16* __restrict__ Bh,
                                              const bf16* __restrict__ Bl,
                                              float* __restrict__ C, int N, int K,
                                              size_t cstride) {
    constexpr int WNW = 8 / WMW;
    constexpr int WROWS = BM / WMW;
    constexpr int WCOLS = 64 / WNW;
    constexpr int N8 = WCOLS / 8;
    constexpr int NB = WCOLS / 16;
    constexpr int AJ = BM / 64;
    extern __shared__ char dsm[];
    bf16* sA = (bf16*)dsm;
    bf16* sB = (bf16*)(dsm + 2 * 2 * BM * 40 * 2);
#define SAi(st, p, r, c) (sA + ((((st)*2 + (p)) * BM + (r)) * 40 + (c)))
#define SBi(st, p, r, c) (sB + ((((st)*2 + (p)) * 32 + (r)) * 72 + (c)))
    int z = blockIdx.z;
    int Ksub = K / gridDim.z;
    Ah += (size_t)z * Ksub;
    Al += (size_t)z * Ksub;
    Bh += (size_t)z * Ksub * N;
    Bl += (size_t)z * Ksub * N;
    C += (size_t)z * cstride;
    int tid = threadIdx.x, lane = tid & 31, warp = tid >> 5;
    int wm = warp % WMW, wn = warp / WMW;
    int bm = blockIdx.y * BM, bn = blockIdx.x * 64;
    int nIt = Ksub >> 5;
    int br = tid >> 3, bc = (tid & 7) << 3;
    const bf16* pBh = Bh + (size_t)br * N + bn + bc;
    const bf16* pBl = Bl + (size_t)br * N + bn + bc;
    float acc[2][N8][4] = {};
#pragma unroll
    for (int j = 0; j < AJ; j++) {
        int id = tid + j * 256, r = id >> 2, c = (id & 3) << 3;
        CPA16(cvta(SAi(0, 0, r, c)), Ah + (size_t)(bm + r) * K + c);
        CPA16(cvta(SAi(0, 1, r, c)), Al + (size_t)(bm + r) * K + c);
    }
    CPA16(cvta(SBi(0, 0, br, bc)), pBh);
    CPA16(cvta(SBi(0, 1, br, bc)), pBl);
    CPCOMMIT();
    for (int it = 0; it < nIt; it++) {
        int st = it & 1;
        if (it + 1 < nIt) {
            int k0 = (it + 1) << 5;
#pragma unroll
            for (int j = 0; j < AJ; j++) {
                int id = tid + j * 256, r = id >> 2, c = (id & 3) << 3;
                CPA16(cvta(SAi(st ^ 1, 0, r, c)), Ah + (size_t)(bm + r) * K + k0 + c);
                CPA16(cvta(SAi(st ^ 1, 1, r, c)), Al + (size_t)(bm + r) * K + k0 + c);
            }
            CPA16(cvta(SBi(st ^ 1, 0, br, bc)), pBh + (size_t)k0 * N);
            CPA16(cvta(SBi(st ^ 1, 1, br, bc)), pBl + (size_t)k0 * N);
            CPCOMMIT(); CPWAIT(1);
        } else CPWAIT(0);
        __syncthreads();
#pragma unroll
        for (int kp = 0; kp < 2; kp++) {
            uint32_t ah2[2][4], al2[2][4], bh2[4 * NB], bl2[4 * NB];
#pragma unroll
            for (int mt = 0; mt < 2; mt++) {
                int r = wm * WROWS + mt * 16 + (lane & 15), c = kp * 16 + ((lane >> 4) << 3);
                LDSM4(ah2[mt], cvta(SAi(st, 0, r, c)));
                LDSM4(al2[mt], cvta(SAi(st, 1, r, c)));
            }
            int bg = lane >> 3;
            int kr = kp * 16 + ((bg & 1) << 3) + (lane & 7);
#pragma unroll
            for (int nb = 0; nb < NB; nb++) {
                int nc = wn * WCOLS + nb * 16 + ((bg >> 1) << 3);
                LDSM4T(&bh2[nb * 4], cvta(SBi(st, 0, kr, nc)));
                LDSM4T(&bl2[nb * 4], cvta(SBi(st, 1, kr, nc)));
            }
#pragma unroll
            for (int mt = 0; mt < 2; mt++)
#pragma unroll
                for (int nt = 0; nt < N8; nt++) {
                    int f = (nt >> 1) * 4 + ((nt & 1) << 1);
                    MMA16(acc[mt][nt], ah2[mt], bh2[f], bh2[f + 1]);
                    MMA16(acc[mt][nt], ah2[mt], bl2[f], bl2[f + 1]);
                    MMA16(acc[mt][nt], al2[mt], bh2[f], bh2[f + 1]);
                }
        }
        __syncthreads();
    }
#pragma unroll
    for (int mt = 0; mt < 2; mt++)
#pragma unroll
        for (int nt = 0; nt < N8; nt++) {
            int r0 = bm + wm * WROWS + mt * 16 + (lane >> 2);
            int c0 = bn + wn * WCOLS + nt * 8 + 2 * (lane & 3);
            *(float2*)(C + (size_t)r0 * N + c0) = make_float2(acc[mt][nt][0], acc[mt][nt][1]);
            *(float2*)(C + (size_t)(r0 + 8) * N + c0) = make_float2(acc[mt][nt][2], acc[mt][nt][3]);
        }
#undef SAi
#undef SBi
}

// ============ dual GEMM (gate|up) + gelu*mul, BM=64 (2m x 4n warps) ============
__global__ void __launch_bounds__(256) k_mmff(const bf16* __restrict__ Ah,
                                              const bf16* __restrict__ Al,
                                              const bf16* __restrict__ B0h,
                                              const bf16* __restrict__ B0l,
                                              const bf16* __restrict__ B1h,
                                              const bf16* __restrict__ B1l,
                                              bf16* __restrict__ Oh, bf16* __restrict__ Ol) {
    extern __shared__ char dsm[];
    bf16* sA = (bf16*)dsm;                                   // [2][2][64][40]
    bf16* sB0 = (bf16*)(dsm + 2 * 2 * 64 * 40 * 2);
    bf16* sB1 = (bf16*)(dsm + 2 * 2 * 64 * 40 * 2 + 2 * 2 * 32 * 72 * 2);
#define SAi(st, p, r, c) (sA + ((((st)*2 + (p)) * 64 + (r)) * 40 + (c)))
#define SB0i(st, p, r, c) (sB0 + ((((st)*2 + (p)) * 32 + (r)) * 72 + (c)))
#define SB1i(st, p, r, c) (sB1 + ((((st)*2 + (p)) * 32 + (r)) * 72 + (c)))
    const int N = FFc, K = Dc;
    int tid = threadIdx.x, lane = tid & 31, warp = tid >> 5;
    int wm = warp & 1, wn = warp >> 1;
    int bm = blockIdx.y * 64, bn = blockIdx.x * 64;
    int br = tid >> 3, bc = (tid & 7) << 3;
    size_t boff = (size_t)br * N + bn + bc;
    float ag[2][2][4] = {}, au[2][2][4] = {};
    {
        int r = tid >> 2, c = (tid & 3) << 3;
        CPA16(cvta(SAi(0, 0, r, c)), Ah + (size_t)(bm + r) * K + c);
        CPA16(cvta(SAi(0, 1, r, c)), Al + (size_t)(bm + r) * K + c);
    }
    CPA16(cvta(SB0i(0, 0, br, bc)), B0h + boff); CPA16(cvta(SB0i(0, 1, br, bc)), B0l + boff);
    CPA16(cvta(SB1i(0, 0, br, bc)), B1h + boff); CPA16(cvta(SB1i(0, 1, br, bc)), B1l + boff);
    CPCOMMIT();
    for (int it = 0; it < (K >> 5); it++) {
        int st = it & 1;
        if (it + 1 < (K >> 5)) {
            int k0 = (it + 1) << 5;
            int r = tid >> 2, c = (tid & 3) << 3;
            CPA16(cvta(SAi(st ^ 1, 0, r, c)), Ah + (size_t)(bm + r) * K + k0 + c);
            CPA16(cvta(SAi(st ^ 1, 1, r, c)), Al + (size_t)(bm + r) * K + k0 + c);
            CPA16(cvta(SB0i(st ^ 1, 0, br, bc)), B0h + boff + (size_t)k0 * N);
            CPA16(cvta(SB0i(st ^ 1, 1, br, bc)), B0l + boff + (size_t)k0 * N);
            CPA16(cvta(SB1i(st ^ 1, 0, br, bc)), B1h + boff + (size_t)k0 * N);
            CPA16(cvta(SB1i(st ^ 1, 1, br, bc)), B1l + boff + (size_t)k0 * N);
            CPCOMMIT(); CPWAIT(1);
        } else CPWAIT(0);
        __syncthreads();
#pragma unroll
        for (int kp = 0; kp < 2; kp++) {
            uint32_t ah2[2][4], al2[2][4], b0h[4], b0l[4], b1h[4], b1l[4];
#pragma unroll
            for (int mt = 0; mt < 2; mt++) {
                int r = wm * 32 + mt * 16 + (lane & 15), c = kp * 16 + ((lane >> 4) << 3);
                LDSM4(ah2[mt], cvta(SAi(st, 0, r, c)));
                LDSM4(al2[mt], cvta(SAi(st, 1, r, c)));
            }
            int bg = lane >> 3;
            int kr = kp * 16 + ((bg & 1) << 3) + (lane & 7);
            int nc = wn * 16 + ((bg >> 1) << 3);
            LDSM4T(b0h, cvta(SB0i(st, 0, kr, nc)));
            LDSM4T(b0l, cvta(SB0i(st, 1, kr, nc)));
            LDSM4T(b1h, cvta(SB1i(st, 0, kr, nc)));
            LDSM4T(b1l, cvta(SB1i(st, 1, kr, nc)));
#pragma unroll
            for (int mt = 0; mt < 2; mt++)
#pragma unroll
                for (int nt = 0; nt < 2; nt++) {
                    MMA16(ag[mt][nt], ah2[mt], b0h[2 * nt], b0h[2 * nt + 1]);
                    MMA16(ag[mt][nt], ah2[mt], b0l[2 * nt], b0l[2 * nt + 1]);
                    MMA16(ag[mt][nt], al2[mt], b0h[2 * nt], b0h[2 * nt + 1]);
                    MMA16(au[mt][nt], ah2[mt], b1h[2 * nt], b1h[2 * nt + 1]);
                    MMA16(au[mt][nt], ah2[mt], b1l[2 * nt], b1l[2 * nt + 1]);
                    MMA16(au[mt][nt], al2[mt], b1h[2 * nt], b1h[2 * nt + 1]);
                }
        }
        __syncthreads();
    }
#pragma unroll
    for (int mt = 0; mt < 2; mt++)
#pragma unroll
        for (int nt = 0; nt < 2; nt++)
#pragma unroll
            for (int e = 0; e < 4; e++) {
                int r0 = bm + wm * 32 + mt * 16 + (lane >> 2) + (e >= 2 ? 8 : 0);
                int c0 = bn + wn * 16 + nt * 8 + 2 * (lane & 3) + (e & 1);
                float x = ag[mt][nt][e];
                float t = tanhf(0.7978845608028654f * (x + 0.044715f * x * x * x));
                splitstore(Oh, Ol, (size_t)r0 * N + c0, 0.5f * x * (1.f + t) * au[mt][nt][e]);
            }
#undef SAi
#undef SB0i
#undef SB1i
}

// ============ flash attention: split-S partials, 2-stage KV pipeline ============
__global__ void __launch_bounds__(256) k_flash(const bf16* __restrict__ kh,
                                               const bf16* __restrict__ kl,
                                               const bf16* __restrict__ vhp,
                                               const bf16* __restrict__ vlp,
                                               float* __restrict__ aop,
                                               float* __restrict__ rsp,
                                               int is_local) {
    extern __shared__ char dsm[];
    bf16* sm = (bf16*)dsm;
    bf16* sQh = sm;
    bf16* sQl = sm + 4608;
    bf16* sKV[2][4];
    sKV[0][0] = sm + 2 * 4608; sKV[0][1] = sm + 3 * 4608;
    sKV[0][2] = sm + 4 * 4608; sKV[0][3] = sm + 5 * 4608;
    sKV[1][0] = sm + 6 * 4608; sKV[1][1] = sm + 7 * 4608;
    sKV[1][2] = sm + 8 * 4608; sKV[1][3] = sm + 9 * 4608;
    bf16* sPh = sm + 10 * 4608;
    bf16* sPl = sm + 11 * 4608;
    float* srs = (float*)(sm + 12 * 4608);
    int h = blockIdx.y, g = h / GSc, t0 = blockIdx.x * 64;
    int z = blockIdx.z;
    int tid = threadIdx.x, lane = tid & 31, warp = tid >> 5;
    int wm = warp & 1, wn = warp >> 1;
    const bf16* Qh_ = bq_h + ((size_t)h * Tc + t0) * HDc;
    const bf16* Ql_ = bq_l + ((size_t)h * Tc + t0) * HDc;
#pragma unroll
    for (int i = 0; i < 2; i++) {
        int c = tid + i * 256, r = c >> 3, cc = (c & 7) << 3;
        CPA16(cvta(sQh + r * 72 + cc), Qh_ + r * HDc + cc);
        CPA16(cvta(sQl + r * 72 + cc), Ql_ + r * HDc + cc);
    }
    if (tid < 64) srs[tid] = 0.f;
    float ao[2][2][4] = {};
    float rs_[2][2] = {};
    int s_lo = is_local ? ((CACHEc + t0 - WINc + 1) >> 6) : 0;
    int s_hi = (CACHEc + t0 + 63) >> 6;
    int nt_all = s_hi - s_lo + 1;
    int half = (nt_all + 1) >> 1;
    int my_lo = (z == 0) ? s_lo : s_lo + half;
    int my_hi = (z == 0) ? s_lo + half - 1 : s_hi;

    auto loadkv = [&](int s0, int st) {
        const bf16* Kh_ = kh + ((size_t)g * Sc + s0) * HDc;
        const bf16* Kl_ = kl + ((size_t)g * Sc + s0) * HDc;
        const bf16* Vh_ = vhp + (size_t)g * HDc * Sc + s0;
        const bf16* Vl_ = vlp + (size_t)g * HDc * Sc + s0;
#pragma unroll
        for (int i = 0; i < 2; i++) {
            int c = tid + i * 256, r = c >> 3, cc = (c & 7) << 3;
            CPA16(cvta(sKV[st][0] + r * 72 + cc), Kh_ + r * HDc + cc);
            CPA16(cvta(sKV[st][1] + r * 72 + cc), Kl_ + r * HDc + cc);
            CPA16(cvta(sKV[st][2] + r * 72 + cc), Vh_ + (size_t)r * Sc + cc);
            CPA16(cvta(sKV[st][3] + r * 72 + cc), Vl_ + (size_t)r * Sc + cc);
        }
    };

    loadkv(my_lo << 6, 0);
    CPCOMMIT();

    for (int stile = my_lo; stile <= my_hi; stile++) {
        int st = (stile - my_lo) & 1;
        int s0 = stile << 6;
        if (stile < my_hi) {
            loadkv((stile + 1) << 6, st ^ 1);
            CPCOMMIT();
            CPWAIT(1);
        } else {
            CPWAIT(0);
        }
        __syncthreads();
        bf16 *cKh = sKV[st][0], *cKl = sKV[st][1], *cVh = sKV[st][2], *cVl = sKV[st][3];
        float sc_[2][2][4] = {};
#pragma unroll
        for (int kp = 0; kp < 4; kp++) {
            uint32_t ah2[2][4], al2[2][4], bh2[4], bl2[4];
#pragma unroll
            for (int mt = 0; mt < 2; mt++) {
                int r = wm * 32 + mt * 16 + (lane & 15), c = kp * 16 + ((lane >> 4) << 3);
                LDSM4(ah2[mt], cvta(sQh + r * 72 + c));
                LDSM4(al2[mt], cvta(sQl + r * 72 + c));
            }
            int bg = lane >> 3;
            int nr = wn * 16 + ((bg >> 1) << 3) + (lane & 7);
            int kc = kp * 16 + ((bg & 1) << 3);
            LDSM4(bh2, cvta(cKh + nr * 72 + kc));
            LDSM4(bl2, cvta(cKl + nr * 72 + kc));
#pragma unroll
            for (int mt = 0; mt < 2; mt++)
#pragma unroll
                for (int nt = 0; nt < 2; nt++) {
                    MMA16(sc_[mt][nt], ah2[mt], bh2[2 * nt], bh2[2 * nt + 1]);
                    MMA16(sc_[mt][nt], ah2[mt], bl2[2 * nt], bl2[2 * nt + 1]);
                    MMA16(sc_[mt][nt], al2[mt], bh2[2 * nt], bh2[2 * nt + 1]);
                }
        }
#pragma unroll
        for (int mt = 0; mt < 2; mt++)
#pragma unroll
            for (int nt = 0; nt < 2; nt++)
#pragma unroll
                for (int e = 0; e < 4; e++) {
                    int tl = wm * 32 + mt * 16 + (lane >> 2) + (e >= 2 ? 8 : 0);
                    int sl = wn * 16 + nt * 8 + 2 * (lane & 3) + (e & 1);
                    int sp = s0 + sl, qpos = CACHEc + t0 + tl;
                    float v = tanhf(sc_[mt][nt][e] * 0.0025f) * 50.f;
                    bool ok = (sp <= qpos) && (!is_local || sp > qpos - WINc);
                    float p = ok ? __expf(v) : 0.f;
                    rs_[mt][e >= 2 ? 1 : 0] += p;
                    bf16 ph = __float2bfloat16(p);
                    sPh[tl * 72 + sl] = ph;
                    sPl[tl * 72 + sl] = __float2bfloat16(p - __bfloat162float(ph));
                }
        __syncthreads();
#pragma unroll
        for (int kp = 0; kp < 4; kp++) {
            uint32_t ah2[2][4], al2[2][4], bh2[4], bl2[4];
#pragma unroll
            for (int mt = 0; mt < 2; mt++) {
                int r = wm * 32 + mt * 16 + (lane & 15), c = kp * 16 + ((lane >> 4) << 3);
                LDSM4(ah2[mt], cvta(sPh + r * 72 + c));
                LDSM4(al2[mt], cvta(sPl + r * 72 + c));
            }
            int bg = lane >> 3;
            int nr = wn * 16 + ((bg >> 1) << 3) + (lane & 7);
            int kc = kp * 16 + ((bg & 1) << 3);
            LDSM4(bh2, cvta(cVh + nr * 72 + kc));
            LDSM4(bl2, cvta(cVl + nr * 72 + kc));
#pragma unroll
            for (int mt = 0; mt < 2; mt++)
#pragma unroll
                for (int nt = 0; nt < 2; nt++) {
                    MMA16(ao[mt][nt], ah2[mt], bh2[2 * nt], bh2[2 * nt + 1]);
                    MMA16(ao[mt][nt], ah2[mt], bl2[2 * nt], bl2[2 * nt + 1]);
                    MMA16(ao[mt][nt], al2[mt], bh2[2 * nt], bh2[2 * nt + 1]);
                }
        }
        __syncthreads();
    }
#pragma unroll
    for (int mt = 0; mt < 2; mt++) {
        atomicAdd(&srs[wm * 32 + mt * 16 + (lane >> 2)], rs_[mt][0]);
        atomicAdd(&srs[wm * 32 + mt * 16 + (lane >> 2) + 8], rs_[mt][1]);
    }
    __syncthreads();
    if (tid < 64)
        rsp[((size_t)z * NHc + h) * Tc + t0 + tid] = srs[tid];
#pragma unroll
    for (int mt = 0; mt < 2; mt++)
#pragma unroll
        for (int nt = 0; nt < 2; nt++) {
            int tl = wm * 32 + mt * 16 + (lane >> 2);
            int d = wn * 16 + nt * 8 + 2 * (lane & 3);
            size_t b0 = (((size_t)z * NHc + h) * Tc + t0 + tl) * HDc + d;
            size_t b1 = (((size_t)z * NHc + h) * Tc + t0 + tl + 8) * HDc + d;
            aop[b0] = ao[mt][nt][0];
            aop[b0 + 1] = ao[mt][nt][1];
            aop[b1] = ao[mt][nt][2];
            aop[b1 + 1] = ao[mt][nt][3];
        }
}

// ---------------- host ----------------
extern "C" void kernel_launch(void* const* d_in, const int* in_sizes, int n_in,
                              void* d_out, int out_size) {
    const float *emb = 0, *kvk = 0, *kvv = 0, *pre_attn = 0, *wqkv = 0, *qnorm = 0,
                *knorm = 0, *wout = 0, *post_attn = 0, *pre_ff = 0, *wgate = 0,
                *wup = 0, *wdown = 0, *post_ff = 0, *finalw = 0, *wlm = 0,
                *cosg = 0, *sing = 0, *cosl = 0, *sinl = 0;
    int kv_n = 0, a = 0, b = 0, c = 0, d = 0;
    for (int i = 0; i < n_in; i++) {
        const float* p = (const float*)d_in[i];
        int s = in_sizes[i];
        if (s == 393216) emb = p;
        else if (s == 10223616) { if (kv_n++ == 0) kvk = p; else kvv = p; }
        else if (s == 19968) { if (a == 0) pre_attn = p; else if (a == 1) post_attn = p; else if (a == 2) pre_ff = p; else post_ff = p; a++; }
        else if (s == SZ_WQKV) wqkv = p;
        else if (s == 1664) { if (b++ == 0) qnorm = p; else knorm = p; }
        else if (s == SZ_WOUT) wout = p;
        else if (s == SZ_WFF) { if (c == 0) wgate = p; else if (c == 1) wup = p; else wdown = p; c++; }
        else if (s == 768) finalw = p;
        else if (s == SZ_WLM) wlm = p;
        else if (s == 32768) { if (d == 0) cosg = p; else if (d == 1) sing = p; else if (d == 2) cosl = p; else sinl = p; d++; }
    }
    float *ph, *pqkv, *pt1, *paop, *prsp;
    bf16 *pxh, *pxl, *path, *patl, *pgh, *pgl, *kh, *kl, *vh, *vl;
    bf16 *qkvh, *qkvl, *outh, *outl, *dnh, *dnl, *lmh, *lml, *gth, *gtl, *uph, *upl;
    cudaGetSymbolAddress((void**)&ph, g_h);
    cudaGetSymbolAddress((void**)&pqkv, g_qkv);
    cudaGetSymbolAddress((void**)&pt1, g_t1);
    cudaGetSymbolAddress((void**)&paop, g_aop);
    cudaGetSymbolAddress((void**)&prsp, g_rsp);
    cudaGetSymbolAddress((void**)&pxh, bx_h); cudaGetSymbolAddress((void**)&pxl, bx_l);
    cudaGetSymbolAddress((void**)&path, bat_h); cudaGetSymbolAddress((void**)&patl, bat_l);
    cudaGetSymbolAddress((void**)&pgh, bgt_h); cudaGetSymbolAddress((void**)&pgl, bgt_l);
    cudaGetSymbolAddress((void**)&kh, bk_h); cudaGetSymbolAddress((void**)&kl, bk_l);
    cudaGetSymbolAddress((void**)&vh, bv_h); cudaGetSymbolAddress((void**)&vl, bv_l);
    cudaGetSymbolAddress((void**)&qkvh, wqkv_h); cudaGetSymbolAddress((void**)&qkvl, wqkv_l);
    cudaGetSymbolAddress((void**)&outh, wout_h); cudaGetSymbolAddress((void**)&outl, wout_l);
    cudaGetSymbolAddress((void**)&gth, wgt_h); cudaGetSymbolAddress((void**)&gtl, wgt_l);
    cudaGetSymbolAddress((void**)&uph, wup_h); cudaGetSymbolAddress((void**)&upl, wup_l);
    cudaGetSymbolAddress((void**)&dnh, wdn_h); cudaGetSymbolAddress((void**)&dnl, wdn_l);
    cudaGetSymbolAddress((void**)&lmh, wlm_h); cudaGetSymbolAddress((void**)&lml, wlm_l);

    const int SM64 = (2 * 2 * 64 * 40 + 2 * 2 * 32 * 72) * 2;
    const int SM128 = (2 * 2 * 128 * 40 + 2 * 2 * 32 * 72) * 2;
    const int SMFF = (2 * 2 * 64 * 40 + 2 * 2 * 2 * 32 * 72) * 2;
    const int SMFL = 12 * 4608 * 2 + 64 * 4;

    cudaFuncSetAttribute(k_mm_t<64, 2>, cudaFuncAttributeMaxDynamicSharedMemorySize, SM64);
    cudaFuncSetAttribute(k_mm_t<128, 4>, cudaFuncAttributeMaxDynamicSharedMemorySize, SM128);
    cudaFuncSetAttribute(k_mmff, cudaFuncAttributeMaxDynamicSharedMemorySize, SMFF);
    cudaFuncSetAttribute(k_flash, cudaFuncAttributeMaxDynamicSharedMemorySize, SMFL);

    // launches 0-2 (flash of layer 0 = launch #5, profiled by ncu -s 5)
    k_split4<<<SZ_WQKV / 4 / 256, 256>>>(wqkv, qkvh, qkvl, SZ_WQKV / 4);          // 0
    k_convall<<<Lc * 196608 / 256, 256>>>(kvk, kvv, kh, kl, vh, vl);              // 1
    k_init<<<Tc, 256>>>(emb, pre_attn, ph, pxh, pxl);                             // 2

    for (int i = 0; i < Lc; i++) {
        int is_local = ((i + 1) % 6 == 0) ? 1 : 0;
        const float* cs = is_local ? cosl : cosg;
        const float* sn = is_local ? sinl : sing;
        bf16* khl = kh + (size_t)i * KVL;
        bf16* kll = kl + (size_t)i * KVL;
        bf16* vhl = vh + (size_t)i * KVL;
        bf16* vll = vl + (size_t)i * KVL;
        k_mm_t<64, 2><<<dim3(QKVW / 64, Tc / 64, 2), 256, SM64>>>(                 // 3
            pxh, pxl, qkvh + (size_t)i * Dc * QKVW, qkvl + (size_t)i * Dc * QKVW,
            pqkv, QKVW, Dc, (size_t)Tc * QKVW);
        k_qkprep<<<dim3(Tc, NGc), HDc>>>(pqkv, qnorm + i * HDc, knorm + i * HDc,   // 4
                                         cs, sn, khl, kll, vhl, vll);
        k_flash<<<dim3(Tc / 64, NHc, 2), 256, SMFL>>>(khl, kll, vhl, vll,          // 5
                                                      paop, prsp, is_local);
        k_fcomb<<<NTD / 256, 256>>>(paop, prsp, path, patl);
        if (i == 0) {
            k_split4<<<SZ_WOUT / 4 / 256, 256>>>(wout, outh, outl, SZ_WOUT / 4);
            k_split4<<<SZ_WFF / 4 / 256, 256>>>(wgate, gth, gtl, SZ_WFF / 4);
            k_split4<<<SZ_WFF / 4 / 256, 256>>>(wup, uph, upl, SZ_WFF / 4);
            k_split4<<<SZ_WFF / 4 / 256, 256>>>(wdown, dnh, dnl, SZ_WFF / 4);
            k_split4<<<SZ_WLM / 4 / 256, 256>>>(wlm, lmh, lml, SZ_WLM / 4);
        }
        k_mm_t<64, 2><<<dim3(Dc / 64, Tc / 64, 2), 256, SM64>>>(
            path, patl, outh + (size_t)i * Dc * Dc, outl + (size_t)i * Dc * Dc,
            pt1, Dc, Dc, (size_t)Tc * Dc);
        k_fuse<<<Tc, 256>>>(ph, pt1, post_attn + i * Dc, pre_ff + i * Dc, pxh, pxl);
        k_mmff<<<dim3(FFc / 64, Tc / 64), 256, SMFF>>>(
            pxh, pxl,
            gth + (size_t)i * Dc * FFc, gtl + (size_t)i * Dc * FFc,
            uph + (size_t)i * Dc * FFc, upl + (size_t)i * Dc * FFc,
            pgh, pgl);
        k_mm_t<64, 2><<<dim3(Dc / 64, Tc / 64, 2), 256, SM64>>>(
            pgh, pgl, dnh + (size_t)i * FFc * Dc, dnl + (size_t)i * FFc * Dc,
            pt1, Dc, FFc, (size_t)Tc * Dc);
        const float* wpre = (i + 1 < Lc) ? pre_attn + (i + 1) * Dc : finalw;
        k_fuse<<<Tc, 256>>>(ph, pt1, post_ff + i * Dc, wpre, pxh, pxl);
    }
    k_mm_t<128, 4><<<dim3(Vocab / 64, Tc / 128, 1), 256, SM128>>>(
        pxh, pxl, lmh, lml, (float*)d_out, Vocab, Dc, 0);
}

// round 11
// speedup vs baseline: 1.4246x; 1.0684x over previous
#include <cuda_runtime.h>
#include <cuda_bf16.h>
#include <math.h>
#include <stdint.h>

#define Lc 26
#define Tc 512
#define Dc 768
#define NHc 12
#define NGc 4
#define GSc 3
#define HDc 64
#define FFc 2048
#define CACHEc 1536
#define Sc 2048
#define Vocab 32000
#define WINc 512
#define QKVW 1280
typedef __nv_bfloat16 bf16;

#define SZ_WQKV 25559040
#define SZ_WOUT 15335424
#define SZ_WFF  40894464
#define SZ_WLM  24576000
#define KVL (NGc * Sc * HDc)
#define NTD (NHc * Tc * HDc)
#define FZ 3                     /* flash split-S factor */
#define TF (Tc * FFc)

// ---------------- scratch ----------------
__device__ float g_h[Tc * Dc];
__device__ float g_qkv[2 * Tc * QKVW];
__device__ float g_t1[2 * Tc * Dc];
__device__ float g_aop[FZ * NTD];
__device__ float g_rsp[FZ * NHc * Tc];
__device__ float g_gp[2 * TF];
__device__ float g_up2[2 * TF];
__device__ bf16 bx_h[Tc * Dc], bx_l[Tc * Dc];
__device__ bf16 bat_h[Tc * Dc], bat_l[Tc * Dc];
__device__ bf16 bgt_h[TF], bgt_l[TF];
__device__ bf16 bq_h[NTD], bq_l[NTD];
__device__ bf16 bk_h[Lc * KVL], bk_l[Lc * KVL];
__device__ bf16 bv_h[Lc * KVL], bv_l[Lc * KVL];
__device__ bf16 wqkv_h[SZ_WQKV], wqkv_l[SZ_WQKV];
__device__ bf16 wout_h[SZ_WOUT], wout_l[SZ_WOUT];
__device__ bf16 wgt_h[SZ_WFF], wgt_l[SZ_WFF];
__device__ bf16 wup_h[SZ_WFF], wup_l[SZ_WFF];
__device__ bf16 wdn_h[SZ_WFF], wdn_l[SZ_WFF];
__device__ bf16 wlm_h[SZ_WLM], wlm_l[SZ_WLM];

// ---------------- asm helpers ----------------
__device__ __forceinline__ uint32_t cvta(const void* p) {
    return (uint32_t)__cvta_generic_to_shared(p);
}
#define LDSM4(r, a) asm volatile( \
    "ldmatrix.sync.aligned.m8n8.x4.shared.b16 {%0,%1,%2,%3},[%4];\n" \
    : "=r"((r)[0]), "=r"((r)[1]), "=r"((r)[2]), "=r"((r)[3]) : "r"(a))
#define LDSM4T(r, a) asm volatile( \
    "ldmatrix.sync.aligned.m8n8.x4.trans.shared.b16 {%0,%1,%2,%3},[%4];\n" \
    : "=r"((r)[0]), "=r"((r)[1]), "=r"((r)[2]), "=r"((r)[3]) : "r"(a))
#define MMA16(c, a, b0, b1) asm volatile( \
    "mma.sync.aligned.m16n8k16.row.col.f32.bf16.bf16.f32 " \
    "{%0,%1,%2,%3},{%4,%5,%6,%7},{%8,%9},{%0,%1,%2,%3};\n" \
    : "+f"((c)[0]), "+f"((c)[1]), "+f"((c)[2]), "+f"((c)[3]) \
    : "r"((a)[0]), "r"((a)[1]), "r"((a)[2]), "r"((a)[3]), "r"(b0), "r"(b1))
#define CPA16(d, s) asm volatile("cp.async.cg.shared.global [%0],[%1],16;\n" :: "r"(d), "l"(s))
#define CPCOMMIT() asm volatile("cp.async.commit_group;\n")
#define CPWAIT(n) asm volatile("cp.async.wait_group %0;\n" :: "n"(n))

__device__ __forceinline__ void splitstore(bf16* ph, bf16* pl, size_t i, float v) {
    bf16 h = __float2bfloat16(v);
    ph[i] = h;
    pl[i] = __float2bfloat16(v - __bfloat162float(h));
}

__device__ __forceinline__ void split4v(float4 v, uint2& hi, uint2& lo) {
    __nv_bfloat162 h0, h1, l0, l1;
    h0.x = __float2bfloat16(v.x); h0.y = __float2bfloat16(v.y);
    h1.x = __float2bfloat16(v.z); h1.y = __float2bfloat16(v.w);
    l0.x = __float2bfloat16(v.x - __bfloat162float(h0.x));
    l0.y = __float2bfloat16(v.y - __bfloat162float(h0.y));
    l1.x = __float2bfloat16(v.z - __bfloat162float(h1.x));
    l1.y = __float2bfloat16(v.w - __bfloat162float(h1.y));
    hi.x = *(uint32_t*)&h0; hi.y = *(uint32_t*)&h1;
    lo.x = *(uint32_t*)&l0; lo.y = *(uint32_t*)&l1;
}

// exp(50*tanh(0.125*s/50)) via identity, exact saturation
__device__ __forceinline__ float softcap_exp(float s) {
    float u = __expf(s * 0.005f);               // e^{2y}, y = 0.0025 s
    return __expf(50.f - 100.f / (u + 1.f));
}
// tanh via exp identity (saturates correctly)
__device__ __forceinline__ float fast_tanh(float y) {
    return 1.f - 2.f / (__expf(2.f * y) + 1.f);
}

__device__ __forceinline__ float blockReduceSum(float v) {
    __shared__ float sh[8];
    __syncthreads();
    int lane = threadIdx.x & 31, w = threadIdx.x >> 5;
#pragma unroll
    for (int o = 16; o; o >>= 1) v += __shfl_down_sync(0xffffffffu, v, o);
    if (lane == 0) sh[w] = v;
    __syncthreads();
    int nw = blockDim.x >> 5;
    if (w == 0) {
        v = (lane < nw) ? sh[lane] : 0.f;
#pragma unroll
        for (int o = 4; o; o >>= 1) v += __shfl_down_sync(0xffffffffu, v, o);
        if (lane == 0) sh[0] = v;
    }
    __syncthreads();
    return sh[0];
}

// ---------------- elementwise ----------------
__global__ void k_split4(const float* __restrict__ s, bf16* __restrict__ hi,
                         bf16* __restrict__ lo, int n4) {
    int i = blockIdx.x * blockDim.x + threadIdx.x;
    if (i >= n4) return;
    float4 v = ((const float4*)s)[i];
    uint2 h, l;
    split4v(v, h, l);
    ((uint2*)hi)[i] = h;
    ((uint2*)lo)[i] = l;
}

__global__ void k_convall(const float* __restrict__ ks, const float* __restrict__ vs,
                          bf16* __restrict__ kh, bf16* __restrict__ kl,
                          bf16* __restrict__ vh, bf16* __restrict__ vl) {
    int idx = blockIdx.x * blockDim.x + threadIdx.x;
    if (idx >= Lc * 196608) return;
    int layer = idx / 196608;
    int r = idx - layer * 196608;
    const float* ksl = ks + (size_t)layer * 393216;
    const float* vsl = vs + (size_t)layer * 393216;
    size_t kvoff = (size_t)layer * KVL;
    if (r < 98304) {
        int i4 = r * 4;
        int g = i4 / (CACHEc * HDc), rr = i4 - g * (CACHEc * HDc);
        size_t dst = kvoff + (size_t)g * Sc * HDc + rr;
        float4 v = ((const float4*)ksl)[r];
        uint2 h, l;
        split4v(v, h, l);
        *(uint2*)(kh + dst) = h;
        *(uint2*)(kl + dst) = l;
    } else {
        int j4 = (r - 98304) * 4;
        int row = j4 / CACHEc, c = j4 - row * CACHEc;
        size_t dst = kvoff + (size_t)row * Sc + c;
        float4 v = ((const float4*)vsl)[r - 98304];
        uint2 h, l;
        split4v(v, h, l);
        *(uint2*)(vh + dst) = h;
        *(uint2*)(vl + dst) = l;
    }
}

__global__ void k_init(const float* __restrict__ e, const float* __restrict__ w,
                       float* __restrict__ h, bf16* __restrict__ oh, bf16* __restrict__ ol) {
    int row = blockIdx.x;
    const float* x = e + row * Dc;
    float ss = 0.f;
    for (int d = threadIdx.x; d < Dc; d += blockDim.x) { float v = x[d]; ss += v * v; }
    float rs = rsqrtf(blockReduceSum(ss) / Dc + 1e-6f);
    for (int d = threadIdx.x; d < Dc; d += blockDim.x) {
        float v = x[d];
        h[row * Dc + d] = v;
        splitstore(oh, ol, (size_t)row * Dc + d, v * rs * (1.f + w[d]));
    }
}

__global__ void k_fuse(float* __restrict__ h, const float* __restrict__ t1,
                       const float* __restrict__ wpost, const float* __restrict__ wpre,
                       bf16* __restrict__ oh, bf16* __restrict__ ol) {
    int row = blockIdx.x;
    const float* x0 = t1 + row * Dc;
    const float* x1 = t1 + Tc * Dc + row * Dc;
    float ss = 0.f;
    for (int d = threadIdx.x; d < Dc; d += blockDim.x) {
        float v = x0[d] + x1[d];
        ss += v * v;
    }
    float rs = rsqrtf(blockReduceSum(ss) / Dc + 1e-6f);
    float ss2 = 0.f;
    for (int d = threadIdx.x; d < Dc; d += blockDim.x) {
        float hv = h[row * Dc + d] + (x0[d] + x1[d]) * rs * (1.f + wpost[d]);
        h[row * Dc + d] = hv;
        ss2 += hv * hv;
    }
    float rs2 = rsqrtf(blockReduceSum(ss2) / Dc + 1e-6f);
    for (int d = threadIdx.x; d < Dc; d += blockDim.x)
        splitstore(oh, ol, (size_t)row * Dc + d, h[row * Dc + d] * rs2 * (1.f + wpre[d]));
}

__global__ void k_qkprep(const float* __restrict__ qkv,
                         const float* __restrict__ qw, const float* __restrict__ kw,
                         const float* __restrict__ cos_, const float* __restrict__ sin_,
                         bf16* __restrict__ kh, bf16* __restrict__ kl,
                         bf16* __restrict__ vh, bf16* __restrict__ vl) {
    int t = blockIdx.x, g = blockIdx.y, d = threadIdx.x;
    size_t boff = ((size_t)(t * NGc + g) * (GSc + 2)) * HDc;
    const float* b0 = qkv + boff;
    const float* b1 = qkv + (size_t)Tc * QKVW + boff;
    __shared__ float sh[HDc];
    __shared__ float r2[2];
    float c = cos_[t * HDc + d], s = sin_[t * HDc + d];
#pragma unroll
    for (int j = 0; j <= GSc; j++) {
        float v = b0[j * HDc + d] + b1[j * HDc + d];
        float sq = v * v;
#pragma unroll
        for (int o = 16; o; o >>= 1) sq += __shfl_down_sync(0xffffffffu, sq, o);
        if ((d & 31) == 0) r2[d >> 5] = sq;
        __syncthreads();
        float rs = rsqrtf((r2[0] + r2[1]) * (1.f / HDc) + 1e-6f);
        const float* wgt = (j < GSc) ? qw : kw;
        float nv = v * rs * (1.f + wgt[d]);
        sh[d] = nv;
        __syncthreads();
        float rot = (d < 32) ? -sh[d + 32] : sh[d - 32];
        float outv = nv * c + rot * s;
        if (j < GSc) splitstore(bq_h, bq_l, ((size_t)(g * GSc + j) * Tc + t) * HDc + d, outv);
        else splitstore(kh, kl, ((size_t)g * Sc + CACHEc + t) * HDc + d, outv);
        __syncthreads();
    }
    float vv = b0[(GSc + 1) * HDc + d] + b1[(GSc + 1) * HDc + d];
    splitstore(vh, vl, (size_t)(g * HDc + d) * Sc + CACHEc + t, vv);
}

// flash combine over FZ partials
__global__ void k_fcomb(const float* __restrict__ aop, const float* __restrict__ rsp,
                        bf16* __restrict__ oh, bf16* __restrict__ ol) {
    int i = blockIdx.x * blockDim.x + threadIdx.x;
    if (i >= NTD) return;
    int h = i / (Tc * HDc);
    int rem = i - h * (Tc * HDc);
    int t = rem / HDc, d = rem - (rem / HDc) * HDc;
    float r = 0.f, o = 0.f;
#pragma unroll
    for (int z = 0; z < FZ; z++) {
        r += rsp[((size_t)z * NHc + h) * Tc + t];
        o += aop[(size_t)z * NTD + i];
    }
    splitstore(oh, ol, (size_t)t * Dc + h * HDc + d, o / r);
}

// ff combine: gelu(g0+g1)*(u0+u1) -> bf16 split
__global__ void k_gcomb(const float* __restrict__ gp, const float* __restrict__ up,
                        bf16* __restrict__ oh, bf16* __restrict__ ol) {
    int i = blockIdx.x * blockDim.x + threadIdx.x;
    if (i >= TF) return;
    float x = gp[i] + gp[TF + i];
    float u = up[i] + up[TF + i];
    float y = 0.7978845608028654f * (x + 0.044715f * x * x * x);
    splitstore(oh, ol, i, 0.5f * x * (1.f + fast_tanh(y)) * u);
}

// ============ templated GEMM: BM x 64 tile, BK=32, split-K via blockIdx.z ============
template <int BM, int WMW>
__global__ void __launch_bounds__(256) k_mm_t(const bf16* __restrict__ Ah,
                                              const bf16* __restrict__ Al,
                                              const bf16* __restrict__ Bh,
                                              const bf16* __restrict__ Bl,
                                              float* __restrict__ C, int N, int K,
                                              size_t cstride) {
    constexpr int WNW = 8 / WMW;
    constexpr int WROWS = BM / WMW;
    constexpr int WCOLS = 64 / WNW;
    constexpr int N8 = WCOLS / 8;
    constexpr int NB = WCOLS / 16;
    constexpr int AJ = BM / 64;
    extern __shared__ char dsm[];
    bf16* sA = (bf16*)dsm;
    bf16* sB = (bf16*)(dsm + 2 * 2 * BM * 40 * 2);
#define SAi(st, p, r, c) (sA + ((((st)*2 + (p)) * BM + (r)) * 40 + (c)))
#define SBi(st, p, r, c) (sB + ((((st)*2 + (p)) * 32 + (r)) * 72 + (c)))
    int z = blockIdx.z;
    int Ksub = K / gridDim.z;
    Ah += (size_t)z * Ksub;
    Al += (size_t)z * Ksub;
    Bh += (size_t)z * Ksub * N;
    Bl += (size_t)z * Ksub * N;
    C += (size_t)z * cstride;
    int tid = threadIdx.x, lane = tid & 31, warp = tid >> 5;
    int wm = warp % WMW, wn = warp / WMW;
    int bm = blockIdx.y * BM, bn = blockIdx.x * 64;
    int nIt = Ksub >> 5;
    int br = tid >> 3, bc = (tid & 7) << 3;
    const bf16* pBh = Bh + (size_t)br * N + bn + bc;
    const bf16* pBl = Bl + (size_t)br * N + bn + bc;
    float acc[2][N8][4] = {};
#pragma unroll
    for (int j = 0; j < AJ; j++) {
        int id = tid + j * 256, r = id >> 2, c = (id & 3) << 3;
        CPA16(cvta(SAi(0, 0, r, c)), Ah + (size_t)(bm + r) * K + c);
        CPA16(cvta(SAi(0, 1, r, c)), Al + (size_t)(bm + r) * K + c);
    }
    CPA16(cvta(SBi(0, 0, br, bc)), pBh);
    CPA16(cvta(SBi(0, 1, br, bc)), pBl);
    CPCOMMIT();
    for (int it = 0; it < nIt; it++) {
        int st = it & 1;
        if (it + 1 < nIt) {
            int k0 = (it + 1) << 5;
#pragma unroll
            for (int j = 0; j < AJ; j++) {
                int id = tid + j * 256, r = id >> 2, c = (id & 3) << 3;
                CPA16(cvta(SAi(st ^ 1, 0, r, c)), Ah + (size_t)(bm + r) * K + k0 + c);
                CPA16(cvta(SAi(st ^ 1, 1, r, c)), Al + (size_t)(bm + r) * K + k0 + c);
            }
            CPA16(cvta(SBi(st ^ 1, 0, br, bc)), pBh + (size_t)k0 * N);
            CPA16(cvta(SBi(st ^ 1, 1, br, bc)), pBl + (size_t)k0 * N);
            CPCOMMIT(); CPWAIT(1);
        } else CPWAIT(0);
        __syncthreads();
#pragma unroll
        for (int kp = 0; kp < 2; kp++) {
            uint32_t ah2[2][4], al2[2][4], bh2[4 * NB], bl2[4 * NB];
#pragma unroll
            for (int mt = 0; mt < 2; mt++) {
                int r = wm * WROWS + mt * 16 + (lane & 15), c = kp * 16 + ((lane >> 4) << 3);
                LDSM4(ah2[mt], cvta(SAi(st, 0, r, c)));
                LDSM4(al2[mt], cvta(SAi(st, 1, r, c)));
            }
            int bg = lane >> 3;
            int kr = kp * 16 + ((bg & 1) << 3) + (lane & 7);
#pragma unroll
            for (int nb = 0; nb < NB; nb++) {
                int nc = wn * WCOLS + nb * 16 + ((bg >> 1) << 3);
                LDSM4T(&bh2[nb * 4], cvta(SBi(st, 0, kr, nc)));
                LDSM4T(&bl2[nb * 4], cvta(SBi(st, 1, kr, nc)));
            }
#pragma unroll
            for (int mt = 0; mt < 2; mt++)
#pragma unroll
                for (int nt = 0; nt < N8; nt++) {
                    int f = (nt >> 1) * 4 + ((nt & 1) << 1);
                    MMA16(acc[mt][nt], ah2[mt], bh2[f], bh2[f + 1]);
                    MMA16(acc[mt][nt], ah2[mt], bl2[f], bl2[f + 1]);
                    MMA16(acc[mt][nt], al2[mt], bh2[f], bh2[f + 1]);
                }
        }
        __syncthreads();
    }
#pragma unroll
    for (int mt = 0; mt < 2; mt++)
#pragma unroll
        for (int nt = 0; nt < N8; nt++) {
            int r0 = bm + wm * WROWS + mt * 16 + (lane >> 2);
            int c0 = bn + wn * WCOLS + nt * 8 + 2 * (lane & 3);
            *(float2*)(C + (size_t)r0 * N + c0) = make_float2(acc[mt][nt][0], acc[mt][nt][1]);
            *(float2*)(C + (size_t)(r0 + 8) * N + c0) = make_float2(acc[mt][nt][2], acc[mt][nt][3]);
        }
#undef SAi
#undef SBi
}

// ============ dual GEMM (gate|up), split-K, fp32 partials ============
__global__ void __launch_bounds__(256) k_mmff(const bf16* __restrict__ Ah,
                                              const bf16* __restrict__ Al,
                                              const bf16* __restrict__ B0h,
                                              const bf16* __restrict__ B0l,
                                              const bf16* __restrict__ B1h,
                                              const bf16* __restrict__ B1l,
                                              float* __restrict__ Cg,
                                              float* __restrict__ Cu) {
    extern __shared__ char dsm[];
    bf16* sA = (bf16*)dsm;
    bf16* sB0 = (bf16*)(dsm + 2 * 2 * 64 * 40 * 2);
    bf16* sB1 = (bf16*)(dsm + 2 * 2 * 64 * 40 * 2 + 2 * 2 * 32 * 72 * 2);
#define SAi(st, p, r, c) (sA + ((((st)*2 + (p)) * 64 + (r)) * 40 + (c)))
#define SB0i(st, p, r, c) (sB0 + ((((st)*2 + (p)) * 32 + (r)) * 72 + (c)))
#define SB1i(st, p, r, c) (sB1 + ((((st)*2 + (p)) * 32 + (r)) * 72 + (c)))
    const int N = FFc, K = Dc;
    int z = blockIdx.z;
    int Ksub = K / gridDim.z;
    const bf16* Ahz = Ah + (size_t)z * Ksub;
    const bf16* Alz = Al + (size_t)z * Ksub;
    const bf16* B0hz = B0h + (size_t)z * Ksub * N;
    const bf16* B0lz = B0l + (size_t)z * Ksub * N;
    const bf16* B1hz = B1h + (size_t)z * Ksub * N;
    const bf16* B1lz = B1l + (size_t)z * Ksub * N;
    Cg += (size_t)z * TF;
    Cu += (size_t)z * TF;
    int tid = threadIdx.x, lane = tid & 31, warp = tid >> 5;
    int wm = warp & 1, wn = warp >> 1;
    int bm = blockIdx.y * 64, bn = blockIdx.x * 64;
    int br = tid >> 3, bc = (tid & 7) << 3;
    size_t boff = (size_t)br * N + bn + bc;
    float ag[2][2][4] = {}, au[2][2][4] = {};
    {
        int r = tid >> 2, c = (tid & 3) << 3;
        CPA16(cvta(SAi(0, 0, r, c)), Ahz + (size_t)(bm + r) * K + c);
        CPA16(cvta(SAi(0, 1, r, c)), Alz + (size_t)(bm + r) * K + c);
    }
    CPA16(cvta(SB0i(0, 0, br, bc)), B0hz + boff); CPA16(cvta(SB0i(0, 1, br, bc)), B0lz + boff);
    CPA16(cvta(SB1i(0, 0, br, bc)), B1hz + boff); CPA16(cvta(SB1i(0, 1, br, bc)), B1lz + boff);
    CPCOMMIT();
    int nIt = Ksub >> 5;
    for (int it = 0; it < nIt; it++) {
        int st = it & 1;
        if (it + 1 < nIt) {
            int k0 = (it + 1) << 5;
            int r = tid >> 2, c = (tid & 3) << 3;
            CPA16(cvta(SAi(st ^ 1, 0, r, c)), Ahz + (size_t)(bm + r) * K + k0 + c);
            CPA16(cvta(SAi(st ^ 1, 1, r, c)), Alz + (size_t)(bm + r) * K + k0 + c);
            CPA16(cvta(SB0i(st ^ 1, 0, br, bc)), B0hz + boff + (size_t)k0 * N);
            CPA16(cvta(SB0i(st ^ 1, 1, br, bc)), B0lz + boff + (size_t)k0 * N);
            CPA16(cvta(SB1i(st ^ 1, 0, br, bc)), B1hz + boff + (size_t)k0 * N);
            CPA16(cvta(SB1i(st ^ 1, 1, br, bc)), B1lz + boff + (size_t)k0 * N);
            CPCOMMIT(); CPWAIT(1);
        } else CPWAIT(0);
        __syncthreads();
#pragma unroll
        for (int kp = 0; kp < 2; kp++) {
            uint32_t ah2[2][4], al2[2][4], b0h[4], b0l[4], b1h[4], b1l[4];
#pragma unroll
            for (int mt = 0; mt < 2; mt++) {
                int r = wm * 32 + mt * 16 + (lane & 15), c = kp * 16 + ((lane >> 4) << 3);
                LDSM4(ah2[mt], cvta(SAi(st, 0, r, c)));
                LDSM4(al2[mt], cvta(SAi(st, 1, r, c)));
            }
            int bg = lane >> 3;
            int kr = kp * 16 + ((bg & 1) << 3) + (lane & 7);
            int nc = wn * 16 + ((bg >> 1) << 3);
            LDSM4T(b0h, cvta(SB0i(st, 0, kr, nc)));
            LDSM4T(b0l, cvta(SB0i(st, 1, kr, nc)));
            LDSM4T(b1h, cvta(SB1i(st, 0, kr, nc)));
            LDSM4T(b1l, cvta(SB1i(st, 1, kr, nc)));
#pragma unroll
            for (int mt = 0; mt < 2; mt++)
#pragma unroll
                for (int nt = 0; nt < 2; nt++) {
                    MMA16(ag[mt][nt], ah2[mt], b0h[2 * nt], b0h[2 * nt + 1]);
                    MMA16(ag[mt][nt], ah2[mt], b0l[2 * nt], b0l[2 * nt + 1]);
                    MMA16(ag[mt][nt], al2[mt], b0h[2 * nt], b0h[2 * nt + 1]);
                    MMA16(au[mt][nt], ah2[mt], b1h[2 * nt], b1h[2 * nt + 1]);
                    MMA16(au[mt][nt], ah2[mt], b1l[2 * nt], b1l[2 * nt + 1]);
                    MMA16(au[mt][nt], al2[mt], b1h[2 * nt], b1h[2 * nt + 1]);
                }
        }
        __syncthreads();
    }
#pragma unroll
    for (int mt = 0; mt < 2; mt++)
#pragma unroll
        for (int nt = 0; nt < 2; nt++) {
            int r0 = bm + wm * 32 + mt * 16 + (lane >> 2);
            int c0 = bn + wn * 16 + nt * 8 + 2 * (lane & 3);
            *(float2*)(Cg + (size_t)r0 * N + c0) = make_float2(ag[mt][nt][0], ag[mt][nt][1]);
            *(float2*)(Cg + (size_t)(r0 + 8) * N + c0) = make_float2(ag[mt][nt][2], ag[mt][nt][3]);
            *(float2*)(Cu + (size_t)r0 * N + c0) = make_float2(au[mt][nt][0], au[mt][nt][1]);
            *(float2*)(Cu + (size_t)(r0 + 8) * N + c0) = make_float2(au[mt][nt][2], au[mt][nt][3]);
        }
#undef SAi
#undef SB0i
#undef SB1i
}

// ============ flash attention: split-S partials, 2-stage KV pipeline ============
__global__ void __launch_bounds__(256) k_flash(const bf16* __restrict__ kh,
                                               const bf16* __restrict__ kl,
                                               const bf16* __restrict__ vhp,
                                               const bf16* __restrict__ vlp,
                                               float* __restrict__ aop,
                                               float* __restrict__ rsp,
                                               int is_local) {
    extern __shared__ char dsm[];
    bf16* sm = (bf16*)dsm;
    bf16* sQh = sm;
    bf16* sQl = sm + 4608;
    bf16* sKV[2][4];
    sKV[0][0] = sm + 2 * 4608; sKV[0][1] = sm + 3 * 4608;
    sKV[0][2] = sm + 4 * 4608; sKV[0][3] = sm + 5 * 4608;
    sKV[1][0] = sm + 6 * 4608; sKV[1][1] = sm + 7 * 4608;
    sKV[1][2] = sm + 8 * 4608; sKV[1][3] = sm + 9 * 4608;
    bf16* sPh = sm + 10 * 4608;
    bf16* sPl = sm + 11 * 4608;
    float* srs = (float*)(sm + 12 * 4608);
    int h = blockIdx.y, g = h / GSc, t0 = blockIdx.x * 64;
    int z = blockIdx.z;
    int tid = threadIdx.x, lane = tid & 31, warp = tid >> 5;
    int wm = warp & 1, wn = warp >> 1;
    const bf16* Qh_ = bq_h + ((size_t)h * Tc + t0) * HDc;
    const bf16* Ql_ = bq_l + ((size_t)h * Tc + t0) * HDc;
#pragma unroll
    for (int i = 0; i < 2; i++) {
        int c = tid + i * 256, r = c >> 3, cc = (c & 7) << 3;
        CPA16(cvta(sQh + r * 72 + cc), Qh_ + r * HDc + cc);
        CPA16(cvta(sQl + r * 72 + cc), Ql_ + r * HDc + cc);
    }
    if (tid < 64) srs[tid] = 0.f;
    float ao[2][2][4] = {};
    float rs_[2][2] = {};
    int s_lo = is_local ? ((CACHEc + t0 - WINc + 1) >> 6) : 0;
    int s_hi = (CACHEc + t0 + 63) >> 6;
    int nt_all = s_hi - s_lo + 1;
    int chunk = (nt_all + (int)gridDim.z - 1) / (int)gridDim.z;
    int my_lo = s_lo + z * chunk;
    int my_hi = my_lo + chunk - 1;
    if (my_hi > s_hi) my_hi = s_hi;

    auto loadkv = [&](int s0, int st) {
        const bf16* Kh_ = kh + ((size_t)g * Sc + s0) * HDc;
        const bf16* Kl_ = kl + ((size_t)g * Sc + s0) * HDc;
        const bf16* Vh_ = vhp + (size_t)g * HDc * Sc + s0;
        const bf16* Vl_ = vlp + (size_t)g * HDc * Sc + s0;
#pragma unroll
        for (int i = 0; i < 2; i++) {
            int c = tid + i * 256, r = c >> 3, cc = (c & 7) << 3;
            CPA16(cvta(sKV[st][0] + r * 72 + cc), Kh_ + r * HDc + cc);
            CPA16(cvta(sKV[st][1] + r * 72 + cc), Kl_ + r * HDc + cc);
            CPA16(cvta(sKV[st][2] + r * 72 + cc), Vh_ + (size_t)r * Sc + cc);
            CPA16(cvta(sKV[st][3] + r * 72 + cc), Vl_ + (size_t)r * Sc + cc);
        }
    };

    if (my_lo <= my_hi) loadkv(my_lo << 6, 0);
    CPCOMMIT();
    __syncthreads();   // srs init visible

    for (int stile = my_lo; stile <= my_hi; stile++) {
        int st = (stile - my_lo) & 1;
        int s0 = stile << 6;
        if (stile < my_hi) {
            loadkv((stile + 1) << 6, st ^ 1);
            CPCOMMIT();
            CPWAIT(1);
        } else {
            CPWAIT(0);
        }
        __syncthreads();
        bf16 *cKh = sKV[st][0], *cKl = sKV[st][1], *cVh = sKV[st][2], *cVl = sKV[st][3];
        float sc_[2][2][4] = {};
#pragma unroll
        for (int kp = 0; kp < 4; kp++) {
            uint32_t ah2[2][4], al2[2][4], bh2[4], bl2[4];
#pragma unroll
            for (int mt = 0; mt < 2; mt++) {
                int r = wm * 32 + mt * 16 + (lane & 15), c = kp * 16 + ((lane >> 4) << 3);
                LDSM4(ah2[mt], cvta(sQh + r * 72 + c));
                LDSM4(al2[mt], cvta(sQl + r * 72 + c));
            }
            int bg = lane >> 3;
            int nr = wn * 16 + ((bg >> 1) << 3) + (lane & 7);
            int kc = kp * 16 + ((bg & 1) << 3);
            LDSM4(bh2, cvta(cKh + nr * 72 + kc));
            LDSM4(bl2, cvta(cKl + nr * 72 + kc));
#pragma unroll
            for (int mt = 0; mt < 2; mt++)
#pragma unroll
                for (int nt = 0; nt < 2; nt++) {
                    MMA16(sc_[mt][nt], ah2[mt], bh2[2 * nt], bh2[2 * nt + 1]);
                    MMA16(sc_[mt][nt], ah2[mt], bl2[2 * nt], bl2[2 * nt + 1]);
                    MMA16(sc_[mt][nt], al2[mt], bh2[2 * nt], bh2[2 * nt + 1]);
                }
        }
#pragma unroll
        for (int mt = 0; mt < 2; mt++)
#pragma unroll
            for (int nt = 0; nt < 2; nt++)
#pragma unroll
                for (int e = 0; e < 4; e++) {
                    int tl = wm * 32 + mt * 16 + (lane >> 2) + (e >= 2 ? 8 : 0);
                    int sl = wn * 16 + nt * 8 + 2 * (lane & 3) + (e & 1);
                    int sp = s0 + sl, qpos = CACHEc + t0 + tl;
                    bool ok = (sp <= qpos) && (!is_local || sp > qpos - WINc);
                    float p = ok ? softcap_exp(sc_[mt][nt][e]) : 0.f;
                    rs_[mt][e >= 2 ? 1 : 0] += p;
                    bf16 ph = __float2bfloat16(p);
                    sPh[tl * 72 + sl] = ph;
                    sPl[tl * 72 + sl] = __float2bfloat16(p - __bfloat162float(ph));
                }
        __syncthreads();
#pragma unroll
        for (int kp = 0; kp < 4; kp++) {
            uint32_t ah2[2][4], al2[2][4], bh2[4], bl2[4];
#pragma unroll
            for (int mt = 0; mt < 2; mt++) {
                int r = wm * 32 + mt * 16 + (lane & 15), c = kp * 16 + ((lane >> 4) << 3);
                LDSM4(ah2[mt], cvta(sPh + r * 72 + c));
                LDSM4(al2[mt], cvta(sPl + r * 72 + c));
            }
            int bg = lane >> 3;
            int nr = wn * 16 + ((bg >> 1) << 3) + (lane & 7);
            int kc = kp * 16 + ((bg & 1) << 3);
            LDSM4(bh2, cvta(cVh + nr * 72 + kc));
            LDSM4(bl2, cvta(cVl + nr * 72 + kc));
#pragma unroll
            for (int mt = 0; mt < 2; mt++)
#pragma unroll
                for (int nt = 0; nt < 2; nt++) {
                    MMA16(ao[mt][nt], ah2[mt], bh2[2 * nt], bh2[2 * nt + 1]);
                    MMA16(ao[mt][nt], ah2[mt], bl2[2 * nt], bl2[2 * nt + 1]);
                    MMA16(ao[mt][nt], al2[mt], bh2[2 * nt], bh2[2 * nt + 1]);
                }
        }
        __syncthreads();
    }
#pragma unroll
    for (int mt = 0; mt < 2; mt++) {
        atomicAdd(&srs[wm * 32 + mt * 16 + (lane >> 2)], rs_[mt][0]);
        atomicAdd(&srs[wm * 32 + mt * 16 + (lane >> 2) + 8], rs_[mt][1]);
    }
    __syncthreads();
    if (tid < 64)
        rsp[((size_t)z * NHc + h) * Tc + t0 + tid] = srs[tid];
#pragma unroll
    for (int mt = 0; mt < 2; mt++)
#pragma unroll
        for (int nt = 0; nt < 2; nt++) {
            int tl = wm * 32 + mt * 16 + (lane >> 2);
            int d = wn * 16 + nt * 8 + 2 * (lane & 3);
            size_t b0 = (((size_t)z * NHc + h) * Tc + t0 + tl) * HDc + d;
            size_t b1 = (((size_t)z * NHc + h) * Tc + t0 + tl + 8) * HDc + d;
            aop[b0] = ao[mt][nt][0];
            aop[b0 + 1] = ao[mt][nt][1];
            aop[b1] = ao[mt][nt][2];
            aop[b1 + 1] = ao[mt][nt][3];
        }
}

// ---------------- host ----------------
extern "C" void kernel_launch(void* const* d_in, const int* in_sizes, int n_in,
                              void* d_out, int out_size) {
    const float *emb = 0, *kvk = 0, *kvv = 0, *pre_attn = 0, *wqkv = 0, *qnorm = 0,
                *knorm = 0, *wout = 0, *post_attn = 0, *pre_ff = 0, *wgate = 0,
                *wup = 0, *wdown = 0, *post_ff = 0, *finalw = 0, *wlm = 0,
                *cosg = 0, *sing = 0, *cosl = 0, *sinl = 0;
    int kv_n = 0, a = 0, b = 0, c = 0, d = 0;
    for (int i = 0; i < n_in; i++) {
        const float* p = (const float*)d_in[i];
        int s = in_sizes[i];
        if (s == 393216) emb = p;
        else if (s == 10223616) { if (kv_n++ == 0) kvk = p; else kvv = p; }
        else if (s == 19968) { if (a == 0) pre_attn = p; else if (a == 1) post_attn = p; else if (a == 2) pre_ff = p; else post_ff = p; a++; }
        else if (s == SZ_WQKV) wqkv = p;
        else if (s == 1664) { if (b++ == 0) qnorm = p; else knorm = p; }
        else if (s == SZ_WOUT) wout = p;
        else if (s == SZ_WFF) { if (c == 0) wgate = p; else if (c == 1) wup = p; else wdown = p; c++; }
        else if (s == 768) finalw = p;
        else if (s == SZ_WLM) wlm = p;
        else if (s == 32768) { if (d == 0) cosg = p; else if (d == 1) sing = p; else if (d == 2) cosl = p; else sinl = p; d++; }
    }
    float *ph, *pqkv, *pt1, *paop, *prsp, *pgp, *pup2;
    bf16 *pxh, *pxl, *path, *patl, *pgh, *pgl, *kh, *kl, *vh, *vl;
    bf16 *qkvh, *qkvl, *outh, *outl, *dnh, *dnl, *lmh, *lml, *gth, *gtl, *uph, *upl;
    cudaGetSymbolAddress((void**)&ph, g_h);
    cudaGetSymbolAddress((void**)&pqkv, g_qkv);
    cudaGetSymbolAddress((void**)&pt1, g_t1);
    cudaGetSymbolAddress((void**)&paop, g_aop);
    cudaGetSymbolAddress((void**)&prsp, g_rsp);
    cudaGetSymbolAddress((void**)&pgp, g_gp);
    cudaGetSymbolAddress((void**)&pup2, g_up2);
    cudaGetSymbolAddress((void**)&pxh, bx_h); cudaGetSymbolAddress((void**)&pxl, bx_l);
    cudaGetSymbolAddress((void**)&path, bat_h); cudaGetSymbolAddress((void**)&patl, bat_l);
    cudaGetSymbolAddress((void**)&pgh, bgt_h); cudaGetSymbolAddress((void**)&pgl, bgt_l);
    cudaGetSymbolAddress((void**)&kh, bk_h); cudaGetSymbolAddress((void**)&kl, bk_l);
    cudaGetSymbolAddress((void**)&vh, bv_h); cudaGetSymbolAddress((void**)&vl, bv_l);
    cudaGetSymbolAddress((void**)&qkvh, wqkv_h); cudaGetSymbolAddress((void**)&qkvl, wqkv_l);
    cudaGetSymbolAddress((void**)&outh, wout_h); cudaGetSymbolAddress((void**)&outl, wout_l);
    cudaGetSymbolAddress((void**)&gth, wgt_h); cudaGetSymbolAddress((void**)&gtl, wgt_l);
    cudaGetSymbolAddress((void**)&uph, wup_h); cudaGetSymbolAddress((void**)&upl, wup_l);
    cudaGetSymbolAddress((void**)&dnh, wdn_h); cudaGetSymbolAddress((void**)&dnl, wdn_l);
    cudaGetSymbolAddress((void**)&lmh, wlm_h); cudaGetSymbolAddress((void**)&lml, wlm_l);

    const int SM64 = (2 * 2 * 64 * 40 + 2 * 2 * 32 * 72) * 2;
    const int SM128 = (2 * 2 * 128 * 40 + 2 * 2 * 32 * 72) * 2;
    const int SMFF = (2 * 2 * 64 * 40 + 2 * 2 * 2 * 32 * 72) * 2;
    const int SMFL = 12 * 4608 * 2 + 64 * 4;

    cudaFuncSetAttribute(k_mm_t<64, 2>, cudaFuncAttributeMaxDynamicSharedMemorySize, SM64);
    cudaFuncSetAttribute(k_mm_t<128, 4>, cudaFuncAttributeMaxDynamicSharedMemorySize, SM128);
    cudaFuncSetAttribute(k_mmff, cudaFuncAttributeMaxDynamicSharedMemorySize, SMFF);
    cudaFuncSetAttribute(k_flash, cudaFuncAttributeMaxDynamicSharedMemorySize, SMFL);

    k_split4<<<SZ_WQKV / 4 / 256, 256>>>(wqkv, qkvh, qkvl, SZ_WQKV / 4);          // 0
    k_convall<<<Lc * 196608 / 256, 256>>>(kvk, kvv, kh, kl, vh, vl);              // 1
    k_init<<<Tc, 256>>>(emb, pre_attn, ph, pxh, pxl);                             // 2

    for (int i = 0; i < Lc; i++) {
        int is_local = ((i + 1) % 6 == 0) ? 1 : 0;
        const float* cs = is_local ? cosl : cosg;
        const float* sn = is_local ? sinl : sing;
        bf16* khl = kh + (size_t)i * KVL;
        bf16* kll = kl + (size_t)i * KVL;
        bf16* vhl = vh + (size_t)i * KVL;
        bf16* vll = vl + (size_t)i * KVL;
        k_mm_t<64, 2><<<dim3(QKVW / 64, Tc / 64, 2), 256, SM64>>>(                 // 3
            pxh, pxl, qkvh + (size_t)i * Dc * QKVW, qkvl + (size_t)i * Dc * QKVW,
            pqkv, QKVW, Dc, (size_t)Tc * QKVW);
        k_qkprep<<<dim3(Tc, NGc), HDc>>>(pqkv, qnorm + i * HDc, knorm + i * HDc,   // 4
                                         cs, sn, khl, kll, vhl, vll);
        k_flash<<<dim3(Tc / 64, NHc, FZ), 256, SMFL>>>(khl, kll, vhl, vll,         // 5
                                                       paop, prsp, is_local);
        k_fcomb<<<NTD / 256, 256>>>(paop, prsp, path, patl);
        if (i == 0) {
            k_split4<<<SZ_WOUT / 4 / 256, 256>>>(wout, outh, outl, SZ_WOUT / 4);
            k_split4<<<SZ_WFF / 4 / 256, 256>>>(wgate, gth, gtl, SZ_WFF / 4);
            k_split4<<<SZ_WFF / 4 / 256, 256>>>(wup, uph, upl, SZ_WFF / 4);
            k_split4<<<SZ_WFF / 4 / 256, 256>>>(wdown, dnh, dnl, SZ_WFF / 4);
            k_split4<<<SZ_WLM / 4 / 256, 256>>>(wlm, lmh, lml, SZ_WLM / 4);
        }
        k_mm_t<64, 2><<<dim3(Dc / 64, Tc / 64, 2), 256, SM64>>>(
            path, patl, outh + (size_t)i * Dc * Dc, outl + (size_t)i * Dc * Dc,
            pt1, Dc, Dc, (size_t)Tc * Dc);
        k_fuse<<<Tc, 256>>>(ph, pt1, post_attn + i * Dc, pre_ff + i * Dc, pxh, pxl);
        k_mmff<<<dim3(FFc / 64, Tc / 64, 2), 256, SMFF>>>(
            pxh, pxl,
            gth + (size_t)i * Dc * FFc, gtl + (size_t)i * Dc * FFc,
            uph + (size_t)i * Dc * FFc, upl + (size_t)i * Dc * FFc,
            pgp, pup2);
        k_gcomb<<<TF / 256, 256>>>(pgp, pup2, pgh, pgl);
        k_mm_t<64, 2><<<dim3(Dc / 64, Tc / 64, 2), 256, SM64>>>(
            pgh, pgl, dnh + (size_t)i * FFc * Dc, dnl + (size_t)i * FFc * Dc,
            pt1, Dc, FFc, (size_t)Tc * Dc);
        const float* wpre = (i + 1 < Lc) ? pre_attn + (i + 1) * Dc : finalw;
        k_fuse<<<Tc, 256>>>(ph, pt1, post_ff + i * Dc, wpre, pxh, pxl);
    }
    k_mm_t<128, 4><<<dim3(Vocab / 64, Tc / 128, 1), 256, SM128>>>(
        pxh, pxl, lmh, lml, (float*)d_out, Vocab, Dc, 0);
}